// round 1
// baseline (speedup 1.0000x reference)
#include <cuda_runtime.h>
#include <math.h>

// ---------------------------------------------------------------------------
// Experts MLP: per expert e in [0,8):
//   rows [e*4096, (e+1)*4096) of flat x[32768,1024]
//   H = gelu_exact(X @ W1[e] + b1[e])    (4096 x 2048)
//   O = H @ W2[e] + b2[e]                (4096 x 1024)
// Flat row order of x and out is identical (reference reshapes are pure views).
// ---------------------------------------------------------------------------

#define BM 128
#define BN 128
#define BK 16
#define TM 8
#define TN 8
// padded leading dim for the transposed A tile (breaks STS bank conflicts,
// keeps 16B alignment for float4 LDS since 132 % 4 == 0)
#define LDA (BM + 4)

static const int E_ = 8;
static const int T_ = 4096;   // rows per expert (b*s)
static const int D_ = 1024;
static const int H_ = 2048;

// scratch for hidden activations: 8 * 4096 * 2048 fp32 = 256 MB
__device__ float g_hidden[(size_t)8 * 4096 * 2048];

__device__ __forceinline__ float gelu_exact(float x) {
    return 0.5f * x * (1.0f + erff(x * 0.70710678118654752f));
}

template <bool DO_GELU>
__global__ __launch_bounds__(256, 2)
void gemm_bias_act(const float* __restrict__ A,   // [E, M, K] row-major
                   const float* __restrict__ B,   // [E, K, N] row-major
                   const float* __restrict__ bias,// [E, N]
                   float* __restrict__ C,         // [E, M, N]
                   int M, int N, int K)
{
    __shared__ float As[BK][LDA];
    __shared__ float Bs[BK][BN];

    const int e = blockIdx.z;
    A    += (size_t)e * M * K;
    B    += (size_t)e * K * N;
    bias += (size_t)e * N;
    C    += (size_t)e * M * N;

    const int tid = threadIdx.x;
    const int tx  = tid & 15;    // 0..15 -> N direction
    const int ty  = tid >> 4;    // 0..15 -> M direction
    const int rowBase = blockIdx.y * BM;
    const int colBase = blockIdx.x * BN;

    float acc[TM][TN];
    #pragma unroll
    for (int i = 0; i < TM; i++)
        #pragma unroll
        for (int j = 0; j < TN; j++)
            acc[i][j] = 0.0f;

    // Per-thread global load coordinates (tile shapes: A 128x16, B 16x128;
    // each = 2048 floats = 512 float4 = 2 float4 per thread)
    for (int kt = 0; kt < K; kt += BK) {
        // ---- load A tile, store transposed As[k][row] ----
        #pragma unroll
        for (int i = 0; i < 2; i++) {
            int idx = tid + i * 256;
            int r   = idx >> 2;          // 0..127
            int kg  = (idx & 3) << 2;    // 0,4,8,12
            float4 v = *reinterpret_cast<const float4*>(
                A + (size_t)(rowBase + r) * K + kt + kg);
            As[kg + 0][r] = v.x;
            As[kg + 1][r] = v.y;
            As[kg + 2][r] = v.z;
            As[kg + 3][r] = v.w;
        }
        // ---- load B tile, Bs[k][col] ----
        #pragma unroll
        for (int i = 0; i < 2; i++) {
            int idx = tid + i * 256;
            int r   = idx >> 5;          // 0..15
            int c   = (idx & 31) << 2;   // 0..124
            *reinterpret_cast<float4*>(&Bs[r][c]) =
                *reinterpret_cast<const float4*>(
                    B + (size_t)(kt + r) * N + colBase + c);
        }
        __syncthreads();

        #pragma unroll
        for (int k = 0; k < BK; k++) {
            float a[TM], b[TN];
            *reinterpret_cast<float4*>(&a[0]) =
                *reinterpret_cast<const float4*>(&As[k][ty * TM]);
            *reinterpret_cast<float4*>(&a[4]) =
                *reinterpret_cast<const float4*>(&As[k][ty * TM + 4]);
            *reinterpret_cast<float4*>(&b[0]) =
                *reinterpret_cast<const float4*>(&Bs[k][tx * TN]);
            *reinterpret_cast<float4*>(&b[4]) =
                *reinterpret_cast<const float4*>(&Bs[k][tx * TN + 4]);
            #pragma unroll
            for (int i = 0; i < TM; i++)
                #pragma unroll
                for (int j = 0; j < TN; j++)
                    acc[i][j] = fmaf(a[i], b[j], acc[i][j]);
        }
        __syncthreads();
    }

    // ---- epilogue: bias (+ exact GELU) + store ----
    float bv[TN];
    #pragma unroll
    for (int j = 0; j < TN; j++)
        bv[j] = bias[colBase + tx * TN + j];

    #pragma unroll
    for (int i = 0; i < TM; i++) {
        const int r = rowBase + ty * TM + i;
        float* crow = C + (size_t)r * N + colBase + tx * TN;
        #pragma unroll
        for (int j = 0; j < TN; j += 4) {
            float4 v;
            v.x = acc[i][j + 0] + bv[j + 0];
            v.y = acc[i][j + 1] + bv[j + 1];
            v.z = acc[i][j + 2] + bv[j + 2];
            v.w = acc[i][j + 3] + bv[j + 3];
            if (DO_GELU) {
                v.x = gelu_exact(v.x);
                v.y = gelu_exact(v.y);
                v.z = gelu_exact(v.z);
                v.w = gelu_exact(v.w);
            }
            *reinterpret_cast<float4*>(crow + j) = v;
        }
    }
}

extern "C" void kernel_launch(void* const* d_in, const int* in_sizes, int n_in,
                              void* d_out, int out_size)
{
    (void)in_sizes; (void)n_in; (void)out_size;
    const float* x  = (const float*)d_in[0];  // [B,E,S,D] flat = [32768,1024]
    const float* w1 = (const float*)d_in[1];  // [8,1024,2048]
    const float* b1 = (const float*)d_in[2];  // [8,2048]
    const float* w2 = (const float*)d_in[3];  // [8,2048,1024]
    const float* b2 = (const float*)d_in[4];  // [8,1024]
    float* out = (float*)d_out;               // [32768,1024]

    float* hidden = nullptr;
    cudaGetSymbolAddress((void**)&hidden, g_hidden);

    dim3 block(256);

    // GEMM1 + bias + exact GELU: [4096x1024] @ [1024x2048] per expert
    dim3 g1(H_ / BN, T_ / BM, E_);
    gemm_bias_act<true><<<g1, block>>>(x, w1, b1, hidden, T_, H_, D_);

    // GEMM2 + bias: [4096x2048] @ [2048x1024] per expert
    dim3 g2(D_ / BN, T_ / BM, E_);
    gemm_bias_act<false><<<g2, block>>>(hidden, w2, b2, out, T_, D_, H_);
}

// round 3
// speedup vs baseline: 1.8190x; 1.8190x over previous
#include <cuda_runtime.h>
#include <cuda_bf16.h>
#include <cstdint>
#include <math.h>

// ============================================================================
// Experts MLP via mma.sync (HMMA) bf16 split-compensated GEMMs.
// (tcgen05 is unavailable: harness emits compute_103 PTX, not sm_103a.)
//   x (fp32) -> x3 bf16 [row][ hi | lo | hi ]              (K'=3072)
//   w1 -> w1t3 bf16 [e][n][ hi | hi | lo ]  (K-major)      (K'=3072)
//   GEMM1: acc = x3 @ w1t3^T (fp32) + b1, exact GELU,
//          epilogue writes h3 [row][ hi | lo | hi ]        (K'=6144)
//   w2 -> w2t3 bf16 [e][n][ hi | hi | lo ]                 (K'=6144)
//   GEMM2: out = h3 @ w2t3^T + b2 (fp32)
// ============================================================================

#define E_ 8
#define T_ 4096
#define D_ 1024
#define H_ 2048

// smem tile geometry: rows of 32 bf16 (64B) padded to 80B (conflict-free ldmatrix)
#define ROWB 80
#define A_BYTES (128 * ROWB)          // 10240
#define STAGE (2 * A_BYTES)           // 20480 (A + B)
#define NSTAGE 4

__device__ __align__(256) __nv_bfloat16 g_x3[(size_t)32768 * 3072];
__device__ __align__(256) __nv_bfloat16 g_w1t3[(size_t)8 * 2048 * 3072];
__device__ __align__(256) __nv_bfloat16 g_h3[(size_t)32768 * 6144];
__device__ __align__(256) __nv_bfloat16 g_w2t3[(size_t)8 * 1024 * 6144];

__device__ __forceinline__ uint32_t smem_u32(const void* p) {
    uint32_t a;
    asm("{ .reg .u64 t; cvta.to.shared.u64 t, %1; cvt.u32.u64 %0, t; }"
        : "=r"(a) : "l"(p));
    return a;
}
__device__ __forceinline__ void cpa16(uint32_t dst, const void* src) {
    asm volatile("cp.async.cg.shared.global [%0], [%1], 16;" :: "r"(dst), "l"(src));
}
__device__ __forceinline__ void ldsm_x4(uint32_t& r0, uint32_t& r1, uint32_t& r2,
                                        uint32_t& r3, uint32_t addr) {
    asm volatile("ldmatrix.sync.aligned.m8n8.x4.shared.b16 {%0,%1,%2,%3}, [%4];"
                 : "=r"(r0), "=r"(r1), "=r"(r2), "=r"(r3) : "r"(addr));
}
__device__ __forceinline__ void mma_bf16(float* c, const uint32_t* a,
                                         uint32_t b0, uint32_t b1) {
    asm volatile(
        "mma.sync.aligned.m16n8k16.row.col.f32.bf16.bf16.f32 "
        "{%0,%1,%2,%3}, {%4,%5,%6,%7}, {%8,%9}, {%0,%1,%2,%3};"
        : "+f"(c[0]), "+f"(c[1]), "+f"(c[2]), "+f"(c[3])
        : "r"(a[0]), "r"(a[1]), "r"(a[2]), "r"(a[3]), "r"(b0), "r"(b1));
}

__device__ __forceinline__ float gelu_exact(float x) {
    return 0.5f * x * (1.0f + erff(x * 0.70710678118654752f));
}
__device__ __forceinline__ void split_bf16(float v, __nv_bfloat16& h, __nv_bfloat16& l) {
    h = __float2bfloat16_rn(v);
    l = __float2bfloat16_rn(v - __bfloat162float(h));
}
__device__ __forceinline__ uint32_t pk(__nv_bfloat16 a, __nv_bfloat16 b) {
    return (uint32_t)__bfloat16_as_ushort(a) | ((uint32_t)__bfloat16_as_ushort(b) << 16);
}

// ============================================================================
// prepasses
// ============================================================================
__global__ void convert_x(const float* __restrict__ x, __nv_bfloat16* __restrict__ x3) {
    size_t gid = (size_t)blockIdx.x * 256 + threadIdx.x;
    size_t base = gid * 4;
    size_t row = base >> 10;
    int c = (int)(base & 1023);
    float4 v = *(const float4*)(x + base);
    __nv_bfloat16 h0, h1, h2, h3, l0, l1, l2, l3;
    split_bf16(v.x, h0, l0); split_bf16(v.y, h1, l1);
    split_bf16(v.z, h2, l2); split_bf16(v.w, h3, l3);
    __nv_bfloat16* orow = x3 + row * 3072;
    uint2 hv = make_uint2(pk(h0, h1), pk(h2, h3));
    uint2 lv = make_uint2(pk(l0, l1), pk(l2, l3));
    *(uint2*)(orow + c)        = hv;
    *(uint2*)(orow + 1024 + c) = lv;
    *(uint2*)(orow + 2048 + c) = hv;
}

// w [E,K,N] fp32 -> wt3 [E,N,3K] bf16 rows = [hi | hi | lo]
__global__ void convert_w(const float* __restrict__ w, __nv_bfloat16* __restrict__ wt3,
                          int K, int N) {
    __shared__ float t[32][33];
    const int e = blockIdx.z;
    const int nb = blockIdx.x * 32, kb = blockIdx.y * 32;
    const float* we = w + (size_t)e * K * N;
    __nv_bfloat16* oe = wt3 + (size_t)e * N * 3 * K;
    const int tx = threadIdx.x, ty = threadIdx.y; // (32, 8)
    #pragma unroll
    for (int i = 0; i < 4; i++)
        t[ty + 8 * i][tx] = we[(size_t)(kb + ty + 8 * i) * N + nb + tx];
    __syncthreads();
    #pragma unroll
    for (int i = 0; i < 4; i++) {
        int n = nb + ty + 8 * i, k = kb + tx;
        float v = t[tx][ty + 8 * i];
        __nv_bfloat16 h, l;
        split_bf16(v, h, l);
        __nv_bfloat16* r = oe + (size_t)n * 3 * K;
        r[k] = h; r[K + k] = h; r[2 * K + k] = l;
    }
}

// ============================================================================
// mma.sync GEMM: C tile 128x128 = A[128,K3] @ B[128,K3]^T, 4-stage cp.async.
// EPI=1: +bias, exact GELU, write h3 split rows [hi|lo|hi]
// EPI=0: +bias, write fp32
// ============================================================================
template <int EPI>
__global__ __launch_bounds__(256, 2)
void gemm_mma(const __nv_bfloat16* __restrict__ A,
              const __nv_bfloat16* __restrict__ B,
              const float* __restrict__ bias,
              float* __restrict__ OutF,
              __nv_bfloat16* __restrict__ OutH,
              int K3, int NBtot)
{
    extern __shared__ __align__(1024) char sm[];  // NSTAGE * STAGE bytes
    __shared__ float s_bias[128];

    const int tid = threadIdx.x;
    const int wid = tid >> 5;
    const int lid = tid & 31;
    const int warp_m = wid >> 2;      // 0..1  -> 64-row half
    const int warp_n = wid & 3;       // 0..3  -> 32-col quarter
    const int e = blockIdx.z;
    const int rowBase = blockIdx.y * 128;
    const int colBase = blockIdx.x * 128;
    const size_t rowGlob0 = (size_t)e * T_ + rowBase;
    const uint32_t smb = smem_u32(sm);

    if (tid < 128) s_bias[tid] = bias[(size_t)e * NBtot + colBase + tid];

    // ---- cp.async slots: A 512 segs of 16B, B 512 segs; 2 + 2 per thread ----
    const char* aG[2]; uint32_t aO[2];
    const char* bG[2]; uint32_t bO[2];
    #pragma unroll
    for (int i = 0; i < 2; i++) {
        int seg = tid + i * 256;
        int r = seg >> 2, g = seg & 3;
        aG[i] = (const char*)(A + (rowGlob0 + r) * (size_t)K3) + g * 16;
        aO[i] = (uint32_t)(r * ROWB + g * 16);
        bG[i] = (const char*)(B + ((size_t)e * NBtot + colBase + r) * (size_t)K3) + g * 16;
        bO[i] = (uint32_t)(A_BYTES + r * ROWB + g * 16);
    }

    // ---- ldmatrix lane addresses (element row within 16, 16B column half) ----
    const int lr = (lid & 7) + ((lid >> 3) & 1) * 8;
    const int lc = (lid >> 4) * 16;
    uint32_t aAdr[4], bAdr[2];
    #pragma unroll
    for (int f = 0; f < 4; f++)
        aAdr[f] = smb + (warp_m * 64 + f * 16 + lr) * ROWB + lc;
    #pragma unroll
    for (int g = 0; g < 2; g++)
        bAdr[g] = smb + A_BYTES + (warp_n * 32 + g * 16 + lr) * ROWB + lc;

    float acc[4][4][4];
    #pragma unroll
    for (int m = 0; m < 4; m++)
        #pragma unroll
        for (int n = 0; n < 4; n++)
            #pragma unroll
            for (int q = 0; q < 4; q++)
                acc[m][n][q] = 0.0f;

    const int NK = K3 / 32;

    auto load_stage = [&](int kt) {
        if (kt < NK) {
            uint32_t sb = smb + (uint32_t)(kt & 3) * STAGE;
            size_t adv = (size_t)kt * 64;  // 32 bf16 per step
            #pragma unroll
            for (int i = 0; i < 2; i++) cpa16(sb + aO[i], aG[i] + adv);
            #pragma unroll
            for (int i = 0; i < 2; i++) cpa16(sb + bO[i], bG[i] + adv);
        }
        asm volatile("cp.async.commit_group;" ::: "memory");
    };

    load_stage(0); load_stage(1); load_stage(2);

    #pragma unroll 1
    for (int kt = 0; kt < NK; kt++) {
        asm volatile("cp.async.wait_group 2;" ::: "memory");
        __syncthreads();
        load_stage(kt + 3);   // overwrites stage (kt-1)&3: safe after the sync

        const uint32_t so = (uint32_t)(kt & 3) * STAGE;
        #pragma unroll
        for (int k16 = 0; k16 < 2; k16++) {
            uint32_t a[4][4], b[2][4];
            #pragma unroll
            for (int f = 0; f < 4; f++)
                ldsm_x4(a[f][0], a[f][1], a[f][2], a[f][3],
                        aAdr[f] + so + k16 * 32);
            #pragma unroll
            for (int g = 0; g < 2; g++)
                ldsm_x4(b[g][0], b[g][1], b[g][2], b[g][3],
                        bAdr[g] + so + k16 * 32);
            #pragma unroll
            for (int m = 0; m < 4; m++)
                #pragma unroll
                for (int n = 0; n < 4; n++)
                    mma_bf16(acc[m][n], a[m], b[n >> 1][n & 1], b[n >> 1][2 + (n & 1)]);
        }
    }
    __syncthreads();

    // ---- epilogue ----
    #pragma unroll
    for (int m = 0; m < 4; m++) {
        const size_t rG = rowGlob0 + warp_m * 64 + m * 16 + (lid >> 2);
        #pragma unroll
        for (int n = 0; n < 4; n++) {
            const int cl = warp_n * 32 + n * 8 + (lid & 3) * 2;  // col in tile
            const float b0 = s_bias[cl], b1 = s_bias[cl + 1];
            const int cg = colBase + cl;
            #pragma unroll
            for (int h = 0; h < 2; h++) {   // h=0: rows rG, h=1: rG+8
                float v0 = acc[m][n][2 * h + 0] + b0;
                float v1 = acc[m][n][2 * h + 1] + b1;
                const size_t rr = rG + h * 8;
                if (EPI == 1) {
                    v0 = gelu_exact(v0); v1 = gelu_exact(v1);
                    __nv_bfloat16 h0, l0, h1, l1;
                    split_bf16(v0, h0, l0); split_bf16(v1, h1, l1);
                    __nv_bfloat16* orow = OutH + rr * (size_t)(3 * NBtot) + cg;
                    uint32_t hv = pk(h0, h1), lv = pk(l0, l1);
                    *(uint32_t*)orow               = hv;
                    *(uint32_t*)(orow + NBtot)     = lv;
                    *(uint32_t*)(orow + 2 * NBtot) = hv;
                } else {
                    float2 v = make_float2(v0, v1);
                    *(float2*)(OutF + rr * (size_t)NBtot + cg) = v;
                }
            }
        }
    }
}

// ============================================================================
extern "C" void kernel_launch(void* const* d_in, const int* in_sizes, int n_in,
                              void* d_out, int out_size)
{
    (void)in_sizes; (void)n_in; (void)out_size;
    const float* x  = (const float*)d_in[0];
    const float* w1 = (const float*)d_in[1];
    const float* b1 = (const float*)d_in[2];
    const float* w2 = (const float*)d_in[3];
    const float* b2 = (const float*)d_in[4];
    float* out = (float*)d_out;

    __nv_bfloat16 *x3, *w1t3, *h3, *w2t3;
    cudaGetSymbolAddress((void**)&x3,   g_x3);
    cudaGetSymbolAddress((void**)&w1t3, g_w1t3);
    cudaGetSymbolAddress((void**)&h3,   g_h3);
    cudaGetSymbolAddress((void**)&w2t3, g_w2t3);

    const int SMEM = NSTAGE * STAGE;   // 81920
    cudaFuncSetAttribute(gemm_mma<1>, cudaFuncAttributeMaxDynamicSharedMemorySize, SMEM);
    cudaFuncSetAttribute(gemm_mma<0>, cudaFuncAttributeMaxDynamicSharedMemorySize, SMEM);

    convert_x<<<32768, 256>>>(x, x3);
    convert_w<<<dim3(H_ / 32, D_ / 32, E_), dim3(32, 8)>>>(w1, w1t3, D_, H_);
    convert_w<<<dim3(D_ / 32, H_ / 32, E_), dim3(32, 8)>>>(w2, w2t3, H_, D_);

    // GEMM1: [4096 x 3072] @ [2048 x 3072]^T + bias + GELU -> h3 (split)
    gemm_mma<1><<<dim3(H_ / 128, T_ / 128, E_), 256, SMEM>>>(
        x3, w1t3, b1, nullptr, h3, 3 * D_, H_);

    // GEMM2: [4096 x 6144] @ [1024 x 6144]^T + bias -> fp32 out
    gemm_mma<0><<<dim3(D_ / 128, T_ / 128, E_), 256, SMEM>>>(
        h3, w2t3, b2, out, nullptr, 3 * H_, D_);
}

// round 4
// speedup vs baseline: 2.4877x; 1.3676x over previous
#include <cuda_runtime.h>
#include <cuda_bf16.h>
#include <cstdint>
#include <math.h>

// ============================================================================
// Experts MLP via mma.sync bf16 split-compensation, term-fused form.
// Operand layout: rows are chunked [hi(32) | lo(32)] bf16 = 128B per k32 chunk.
//   x  -> x2  [32768][2*1024]   (K=1024, 32 chunks)
//   w1 -> w1t2 [e][n][2*1024]   (K-major, transposed)
//   GEMM1: acc = hiA*hiB + loA*hiB + hiA*loB  (fp32), +b1, exact GELU
//          -> h2 [32768][2*2048] (chunked split)
//   w2 -> w2t2 [e][n][2*2048]
//   GEMM2: same 3-term MMA, +b2 -> fp32 out
// ============================================================================

#define E_ 8
#define T_ 4096
#define D_ 1024
#define H_ 2048

#define A_BYTES 16384              // 128 rows * 128B
#define STAGE   32768              // A + B tile
#define NSTAGE  3

__device__ __align__(256) __nv_bfloat16 g_x2[(size_t)32768 * 2048];        // 128MB
__device__ __align__(256) __nv_bfloat16 g_w1t2[(size_t)8 * 2048 * 2048];   //  64MB
__device__ __align__(256) __nv_bfloat16 g_h2[(size_t)32768 * 4096];        // 256MB
__device__ __align__(256) __nv_bfloat16 g_w2t2[(size_t)8 * 1024 * 4096];   //  64MB

__device__ __forceinline__ uint32_t smem_u32(const void* p) {
    uint32_t a;
    asm("{ .reg .u64 t; cvta.to.shared.u64 t, %1; cvt.u32.u64 %0, t; }"
        : "=r"(a) : "l"(p));
    return a;
}
__device__ __forceinline__ void cpa16(uint32_t dst, const void* src) {
    asm volatile("cp.async.cg.shared.global [%0], [%1], 16;" :: "r"(dst), "l"(src));
}
__device__ __forceinline__ void ldsm_x4(uint32_t* r, uint32_t addr) {
    asm volatile("ldmatrix.sync.aligned.m8n8.x4.shared.b16 {%0,%1,%2,%3}, [%4];"
                 : "=r"(r[0]), "=r"(r[1]), "=r"(r[2]), "=r"(r[3]) : "r"(addr));
}
__device__ __forceinline__ void mma_bf16(float* c, const uint32_t* a,
                                         uint32_t b0, uint32_t b1) {
    asm volatile(
        "mma.sync.aligned.m16n8k16.row.col.f32.bf16.bf16.f32 "
        "{%0,%1,%2,%3}, {%4,%5,%6,%7}, {%8,%9}, {%0,%1,%2,%3};"
        : "+f"(c[0]), "+f"(c[1]), "+f"(c[2]), "+f"(c[3])
        : "r"(a[0]), "r"(a[1]), "r"(a[2]), "r"(a[3]), "r"(b0), "r"(b1));
}

__device__ __forceinline__ float gelu_exact(float x) {
    return 0.5f * x * (1.0f + erff(x * 0.70710678118654752f));
}
__device__ __forceinline__ void split_bf16(float v, __nv_bfloat16& h, __nv_bfloat16& l) {
    h = __float2bfloat16_rn(v);
    l = __float2bfloat16_rn(v - __bfloat162float(h));
}
__device__ __forceinline__ uint32_t pk(__nv_bfloat16 a, __nv_bfloat16 b) {
    return (uint32_t)__bfloat16_as_ushort(a) | ((uint32_t)__bfloat16_as_ushort(b) << 16);
}

// ============================================================================
// prepasses
// ============================================================================
// x row [1024 fp32] -> x2 row [2048 bf16] chunked [hi32|lo32]
__global__ void convert_x(const float* __restrict__ x, __nv_bfloat16* __restrict__ x2) {
    size_t gid = (size_t)blockIdx.x * 256 + threadIdx.x;
    size_t base = gid * 4;
    size_t row = base >> 10;
    int c = (int)(base & 1023);
    float4 v = *(const float4*)(x + base);
    __nv_bfloat16 h0, h1, h2, h3, l0, l1, l2, l3;
    split_bf16(v.x, h0, l0); split_bf16(v.y, h1, l1);
    split_bf16(v.z, h2, l2); split_bf16(v.w, h3, l3);
    __nv_bfloat16* orow = x2 + row * 2048 + (size_t)(c >> 5) * 64 + (c & 31);
    *(uint2*)orow        = make_uint2(pk(h0, h1), pk(h2, h3));
    *(uint2*)(orow + 32) = make_uint2(pk(l0, l1), pk(l2, l3));
}

// w [E,K,N] fp32 -> wt2 [E,N,2K] chunked [hi32|lo32] along k
__global__ void convert_w(const float* __restrict__ w, __nv_bfloat16* __restrict__ wt2,
                          int K, int N) {
    __shared__ float t[32][33];
    const int e = blockIdx.z;
    const int nb = blockIdx.x * 32, kb = blockIdx.y * 32;
    const float* we = w + (size_t)e * K * N;
    __nv_bfloat16* oe = wt2 + (size_t)e * N * 2 * K;
    const int tx = threadIdx.x, ty = threadIdx.y; // (32, 8)
    #pragma unroll
    for (int i = 0; i < 4; i++)
        t[ty + 8 * i][tx] = we[(size_t)(kb + ty + 8 * i) * N + nb + tx];
    __syncthreads();
    #pragma unroll
    for (int i = 0; i < 4; i++) {
        int n = nb + ty + 8 * i, k = kb + tx;
        float v = t[tx][ty + 8 * i];
        __nv_bfloat16 h, l;
        split_bf16(v, h, l);
        __nv_bfloat16* r = oe + (size_t)n * 2 * K + (size_t)(k >> 5) * 64 + (k & 31);
        r[0] = h; r[32] = l;
    }
}

// ============================================================================
// GEMM: C tile 128x128; per chunk (k32) load one A + one B tile [hi|lo],
// issue 3 MMA combos. 3-stage cp.async pipeline, SW128 swizzle.
// ============================================================================
template <int EPI>
__global__ __launch_bounds__(256, 2)
void gemm_mma(const __nv_bfloat16* __restrict__ A,
              const __nv_bfloat16* __restrict__ B,
              const float* __restrict__ bias,
              float* __restrict__ OutF,
              __nv_bfloat16* __restrict__ OutH,
              int Kr, int NBtot)
{
    extern __shared__ __align__(1024) char sm[];   // NSTAGE * STAGE
    __shared__ float s_bias[128];

    const int tid = threadIdx.x;
    const int wid = tid >> 5;
    const int lid = tid & 31;
    const int warp_m = wid >> 2;     // 0..1
    const int warp_n = wid & 3;      // 0..3
    const int e = blockIdx.z;
    const int rowBase = blockIdx.y * 128;
    const int colBase = blockIdx.x * 128;
    const size_t rowGlob0 = (size_t)e * T_ + rowBase;
    const uint32_t smb = smem_u32(sm);
    const size_t rowLen = (size_t)2 * Kr;          // bf16 per row

    if (tid < 128) s_bias[tid] = bias[(size_t)e * NBtot + colBase + tid];

    // ---- cp.async: A tile 1024 segs of 16B, B tile 1024 segs; 4+4 per thread.
    // seg i: row r = (tid>>3) + 32*i, col g = tid&7. Row-delta folds into a
    // constant stride; swizzle XOR depends only on r&7 (invariant across i).
    const int r0 = tid >> 3, g0 = tid & 7;
    const char* aG0 = (const char*)(A + (rowGlob0 + r0) * rowLen) + g0 * 16;
    const char* bG0 = (const char*)(B + ((size_t)e * NBtot + colBase + r0) * rowLen) + g0 * 16;
    const size_t gStride = 32 * rowLen * 2;        // bytes between seg rows
    const uint32_t sO0 = (uint32_t)(r0 * 128 + ((g0 << 4) ^ ((r0 & 7) << 4)));

    // ---- ldmatrix addressing ----
    const int lr = (lid & 7) + ((lid >> 3) & 1) * 8;  // row 0..15 within frag grp
    const uint32_t lcol = ((lid >> 4) & 1) << 4;      // 0 or 16
    const uint32_t xr = (uint32_t)(lr & 7) << 4;
    const uint32_t arb0 = (uint32_t)(warp_m * 64 + lr) * 128;
    const uint32_t brb0 = (uint32_t)(warp_n * 32 + lr) * 128 + A_BYTES;

    float acc[4][4][4];
    #pragma unroll
    for (int m = 0; m < 4; m++)
        #pragma unroll
        for (int n = 0; n < 4; n++)
            #pragma unroll
            for (int q = 0; q < 4; q++)
                acc[m][n][q] = 0.0f;

    const int NK = Kr / 32;

    auto load_stage = [&](int kt, int s) {
        if (kt < NK) {
            uint32_t sb = smb + (uint32_t)s * STAGE + sO0;
            size_t adv = (size_t)kt * 128;
            #pragma unroll
            for (int i = 0; i < 4; i++)
                cpa16(sb + i * 4096, aG0 + i * gStride + adv);
            #pragma unroll
            for (int i = 0; i < 4; i++)
                cpa16(sb + A_BYTES + i * 4096, bG0 + i * gStride + adv);
        }
        asm volatile("cp.async.commit_group;" ::: "memory");
    };

    load_stage(0, 0);
    load_stage(1, 1);

    int cs = 0, ls = 2;
    #pragma unroll 1
    for (int kt = 0; kt < NK; kt++) {
        asm volatile("cp.async.wait_group 1;" ::: "memory");
        __syncthreads();
        load_stage(kt + 2, ls);
        if (++ls == NSTAGE) ls = 0;

        const uint32_t so = smb + (uint32_t)cs * STAGE;
        if (++cs == NSTAGE) cs = 0;

        #pragma unroll
        for (int sub = 0; sub < 2; sub++) {
            const uint32_t chi = ((uint32_t)(sub << 5) | lcol) ^ xr;
            const uint32_t clo = ((uint32_t)(sub << 5) | lcol | 64u) ^ xr;

            uint32_t ah[4][4], bh[2][4], al[4][4], bl[2][4];
            #pragma unroll
            for (int f = 0; f < 4; f++)
                ldsm_x4(ah[f], so + arb0 + f * 2048 + chi);
            #pragma unroll
            for (int g = 0; g < 2; g++)
                ldsm_x4(bh[g], so + brb0 + g * 2048 + chi);
            #pragma unroll
            for (int f = 0; f < 4; f++)
                ldsm_x4(al[f], so + arb0 + f * 2048 + clo);

            #pragma unroll
            for (int m = 0; m < 4; m++)
                #pragma unroll
                for (int n = 0; n < 4; n++)
                    mma_bf16(acc[m][n], ah[m], bh[n >> 1][n & 1], bh[n >> 1][2 + (n & 1)]);

            #pragma unroll
            for (int g = 0; g < 2; g++)
                ldsm_x4(bl[g], so + brb0 + g * 2048 + clo);

            #pragma unroll
            for (int m = 0; m < 4; m++)
                #pragma unroll
                for (int n = 0; n < 4; n++)
                    mma_bf16(acc[m][n], al[m], bh[n >> 1][n & 1], bh[n >> 1][2 + (n & 1)]);

            #pragma unroll
            for (int m = 0; m < 4; m++)
                #pragma unroll
                for (int n = 0; n < 4; n++)
                    mma_bf16(acc[m][n], ah[m], bl[n >> 1][n & 1], bl[n >> 1][2 + (n & 1)]);
        }
    }
    __syncthreads();

    // ---- epilogue ----
    #pragma unroll
    for (int m = 0; m < 4; m++) {
        const size_t rG = rowGlob0 + warp_m * 64 + m * 16 + (lid >> 2);
        #pragma unroll
        for (int n = 0; n < 4; n++) {
            const int cl = warp_n * 32 + n * 8 + (lid & 3) * 2;
            const float b0 = s_bias[cl], b1 = s_bias[cl + 1];
            const int cg = colBase + cl;
            #pragma unroll
            for (int h = 0; h < 2; h++) {
                float v0 = acc[m][n][2 * h + 0] + b0;
                float v1 = acc[m][n][2 * h + 1] + b1;
                const size_t rr = rG + h * 8;
                if (EPI == 1) {
                    v0 = gelu_exact(v0); v1 = gelu_exact(v1);
                    __nv_bfloat16 h0, l0, h1, l1;
                    split_bf16(v0, h0, l0); split_bf16(v1, h1, l1);
                    __nv_bfloat16* orow = OutH + rr * (size_t)(2 * NBtot)
                                        + (size_t)(cg >> 5) * 64 + (cg & 31);
                    *(uint32_t*)orow        = pk(h0, h1);
                    *(uint32_t*)(orow + 32) = pk(l0, l1);
                } else {
                    *(float2*)(OutF + rr * (size_t)NBtot + cg) = make_float2(v0, v1);
                }
            }
        }
    }
}

// ============================================================================
extern "C" void kernel_launch(void* const* d_in, const int* in_sizes, int n_in,
                              void* d_out, int out_size)
{
    (void)in_sizes; (void)n_in; (void)out_size;
    const float* x  = (const float*)d_in[0];
    const float* w1 = (const float*)d_in[1];
    const float* b1 = (const float*)d_in[2];
    const float* w2 = (const float*)d_in[3];
    const float* b2 = (const float*)d_in[4];
    float* out = (float*)d_out;

    __nv_bfloat16 *x2, *w1t2, *h2, *w2t2;
    cudaGetSymbolAddress((void**)&x2,   g_x2);
    cudaGetSymbolAddress((void**)&w1t2, g_w1t2);
    cudaGetSymbolAddress((void**)&h2,   g_h2);
    cudaGetSymbolAddress((void**)&w2t2, g_w2t2);

    const int SMEM = NSTAGE * STAGE;   // 98304
    cudaFuncSetAttribute(gemm_mma<1>, cudaFuncAttributeMaxDynamicSharedMemorySize, SMEM);
    cudaFuncSetAttribute(gemm_mma<0>, cudaFuncAttributeMaxDynamicSharedMemorySize, SMEM);

    convert_x<<<32768, 256>>>(x, x2);
    convert_w<<<dim3(H_ / 32, D_ / 32, E_), dim3(32, 8)>>>(w1, w1t2, D_, H_);
    convert_w<<<dim3(D_ / 32, H_ / 32, E_), dim3(32, 8)>>>(w2, w2t2, H_, D_);

    // GEMM1: K=1024, N=2048, +bias+GELU -> h2 (chunked split)
    gemm_mma<1><<<dim3(H_ / 128, T_ / 128, E_), 256, SMEM>>>(
        x2, w1t2, b1, nullptr, h2, D_, H_);

    // GEMM2: K=2048, N=1024, +bias -> fp32 out
    gemm_mma<0><<<dim3(D_ / 128, T_ / 128, E_), 256, SMEM>>>(
        h2, w2t2, b2, out, nullptr, H_, D_);
}

// round 5
// speedup vs baseline: 2.5809x; 1.0375x over previous
#include <cuda_runtime.h>
#include <cuda_bf16.h>
#include <cstdint>
#include <math.h>

// ============================================================================
// Experts MLP via mma.sync bf16 split-compensation, term-fused form.
// Operand layout: rows chunked [hi(32) | lo(32)] bf16 = 128B per k32 chunk.
// Inner loop reordered t1,t3,t2 so LDSM interleaves with MMA (LDS pipe and
// tensor pipe run concurrently) and the per-chunk barrier is hidden behind
// a register-only MMA block.
// ============================================================================

#define E_ 8
#define T_ 4096
#define D_ 1024
#define H_ 2048

#define A_BYTES 16384              // 128 rows * 128B
#define STAGE   32768              // A + B tile
#define NSTAGE  3

__device__ __align__(256) __nv_bfloat16 g_x2[(size_t)32768 * 2048];
__device__ __align__(256) __nv_bfloat16 g_w1t2[(size_t)8 * 2048 * 2048];
__device__ __align__(256) __nv_bfloat16 g_h2[(size_t)32768 * 4096];
__device__ __align__(256) __nv_bfloat16 g_w2t2[(size_t)8 * 1024 * 4096];

__device__ __forceinline__ uint32_t smem_u32(const void* p) {
    uint32_t a;
    asm("{ .reg .u64 t; cvta.to.shared.u64 t, %1; cvt.u32.u64 %0, t; }"
        : "=r"(a) : "l"(p));
    return a;
}
__device__ __forceinline__ void cpa16(uint32_t dst, const void* src) {
    asm volatile("cp.async.cg.shared.global [%0], [%1], 16;" :: "r"(dst), "l"(src));
}
__device__ __forceinline__ void ldsm_x4(uint32_t* r, uint32_t addr) {
    asm volatile("ldmatrix.sync.aligned.m8n8.x4.shared.b16 {%0,%1,%2,%3}, [%4];"
                 : "=r"(r[0]), "=r"(r[1]), "=r"(r[2]), "=r"(r[3]) : "r"(addr));
}
__device__ __forceinline__ void mma_bf16(float* c, const uint32_t* a,
                                         uint32_t b0, uint32_t b1) {
    asm volatile(
        "mma.sync.aligned.m16n8k16.row.col.f32.bf16.bf16.f32 "
        "{%0,%1,%2,%3}, {%4,%5,%6,%7}, {%8,%9}, {%0,%1,%2,%3};"
        : "+f"(c[0]), "+f"(c[1]), "+f"(c[2]), "+f"(c[3])
        : "r"(a[0]), "r"(a[1]), "r"(a[2]), "r"(a[3]), "r"(b0), "r"(b1));
}

__device__ __forceinline__ float gelu_exact(float x) {
    return 0.5f * x * (1.0f + erff(x * 0.70710678118654752f));
}
__device__ __forceinline__ void split_bf16(float v, __nv_bfloat16& h, __nv_bfloat16& l) {
    h = __float2bfloat16_rn(v);
    l = __float2bfloat16_rn(v - __bfloat162float(h));
}
__device__ __forceinline__ uint32_t pk(__nv_bfloat16 a, __nv_bfloat16 b) {
    return (uint32_t)__bfloat16_as_ushort(a) | ((uint32_t)__bfloat16_as_ushort(b) << 16);
}

// ============================================================================
// prepasses
// ============================================================================
__global__ void convert_x(const float* __restrict__ x, __nv_bfloat16* __restrict__ x2) {
    size_t gid = (size_t)blockIdx.x * 256 + threadIdx.x;
    size_t base = gid * 4;
    size_t row = base >> 10;
    int c = (int)(base & 1023);
    float4 v = *(const float4*)(x + base);
    __nv_bfloat16 h0, h1, h2, h3, l0, l1, l2, l3;
    split_bf16(v.x, h0, l0); split_bf16(v.y, h1, l1);
    split_bf16(v.z, h2, l2); split_bf16(v.w, h3, l3);
    __nv_bfloat16* orow = x2 + row * 2048 + (size_t)(c >> 5) * 64 + (c & 31);
    *(uint2*)orow        = make_uint2(pk(h0, h1), pk(h2, h3));
    *(uint2*)(orow + 32) = make_uint2(pk(l0, l1), pk(l2, l3));
}

__global__ void convert_w(const float* __restrict__ w, __nv_bfloat16* __restrict__ wt2,
                          int K, int N) {
    __shared__ float t[32][33];
    const int e = blockIdx.z;
    const int nb = blockIdx.x * 32, kb = blockIdx.y * 32;
    const float* we = w + (size_t)e * K * N;
    __nv_bfloat16* oe = wt2 + (size_t)e * N * 2 * K;
    const int tx = threadIdx.x, ty = threadIdx.y; // (32, 8)
    #pragma unroll
    for (int i = 0; i < 4; i++)
        t[ty + 8 * i][tx] = we[(size_t)(kb + ty + 8 * i) * N + nb + tx];
    __syncthreads();
    #pragma unroll
    for (int i = 0; i < 4; i++) {
        int n = nb + ty + 8 * i, k = kb + tx;
        float v = t[tx][ty + 8 * i];
        __nv_bfloat16 h, l;
        split_bf16(v, h, l);
        __nv_bfloat16* r = oe + (size_t)n * 2 * K + (size_t)(k >> 5) * 64 + (k & 31);
        r[0] = h; r[32] = l;
    }
}

// ============================================================================
// GEMM: C tile 128x128; 3-term split MMA, 3-stage cp.async, interleaved LDSM.
// ============================================================================
template <int EPI>
__global__ __launch_bounds__(256, 2)
void gemm_mma(const __nv_bfloat16* __restrict__ A,
              const __nv_bfloat16* __restrict__ B,
              const float* __restrict__ bias,
              float* __restrict__ OutF,
              __nv_bfloat16* __restrict__ OutH,
              int Kr, int NBtot)
{
    extern __shared__ __align__(1024) char sm[];
    __shared__ float s_bias[128];

    const int tid = threadIdx.x;
    const int wid = tid >> 5;
    const int lid = tid & 31;
    const int warp_m = wid >> 2;
    const int warp_n = wid & 3;
    const int e = blockIdx.z;
    const int rowBase = blockIdx.y * 128;
    const int colBase = blockIdx.x * 128;
    const size_t rowGlob0 = (size_t)e * T_ + rowBase;
    const uint32_t smb = smem_u32(sm);
    const size_t rowLen = (size_t)2 * Kr;

    if (tid < 128) s_bias[tid] = bias[(size_t)e * NBtot + colBase + tid];

    // cp.async slots
    const int r0 = tid >> 3, g0 = tid & 7;
    const char* aG0 = (const char*)(A + (rowGlob0 + r0) * rowLen) + g0 * 16;
    const char* bG0 = (const char*)(B + ((size_t)e * NBtot + colBase + r0) * rowLen) + g0 * 16;
    const size_t gStride = 32 * rowLen * 2;
    const uint32_t sO0 = (uint32_t)(r0 * 128 + ((g0 << 4) ^ ((r0 & 7) << 4)));

    // ldmatrix addressing
    const int lr = (lid & 7) + ((lid >> 3) & 1) * 8;
    const uint32_t lcol = ((lid >> 4) & 1) << 4;
    const uint32_t xr = (uint32_t)(lr & 7) << 4;
    const uint32_t arb0 = (uint32_t)(warp_m * 64 + lr) * 128;
    const uint32_t brb0 = (uint32_t)(warp_n * 32 + lr) * 128 + A_BYTES;

    const uint32_t chi0 = lcol ^ xr;           // sub0 hi cols
    const uint32_t chi1 = (32u | lcol) ^ xr;   // sub1 hi cols
    const uint32_t clo0 = chi0 ^ 64u;
    const uint32_t clo1 = chi1 ^ 64u;

    float acc[4][4][4];
    #pragma unroll
    for (int m = 0; m < 4; m++)
        #pragma unroll
        for (int n = 0; n < 4; n++)
            #pragma unroll
            for (int q = 0; q < 4; q++)
                acc[m][n][q] = 0.0f;

    const int NK = Kr / 32;

    auto load_stage = [&](int kt, int s) {
        if (kt < NK) {
            uint32_t sb = smb + (uint32_t)s * STAGE + sO0;
            size_t adv = (size_t)kt * 128;
            #pragma unroll
            for (int i = 0; i < 4; i++)
                cpa16(sb + i * 4096, aG0 + i * gStride + adv);
            #pragma unroll
            for (int i = 0; i < 4; i++)
                cpa16(sb + A_BYTES + i * 4096, bG0 + i * gStride + adv);
        }
        asm volatile("cp.async.commit_group;" ::: "memory");
    };

    auto ldA = [&](uint32_t st, uint32_t col, uint32_t (&fr)[4][4]) {
        #pragma unroll
        for (int f = 0; f < 4; f++)
            ldsm_x4(fr[f], st + arb0 + f * 2048 + col);
    };
    auto ldB = [&](uint32_t st, uint32_t col, uint32_t (&fr)[2][4]) {
        #pragma unroll
        for (int g = 0; g < 2; g++)
            ldsm_x4(fr[g], st + brb0 + g * 2048 + col);
    };
    auto mmaT = [&](const uint32_t (&a)[4][4], const uint32_t (&b)[2][4]) {
        #pragma unroll
        for (int m = 0; m < 4; m++)
            #pragma unroll
            for (int n = 0; n < 4; n++)
                mma_bf16(acc[m][n], a[m], b[n >> 1][n & 1], b[n >> 1][2 + (n & 1)]);
    };

    // prologue: fill all 3 stages, then preload sub0 hi frags of chunk 0
    load_stage(0, 0); load_stage(1, 1); load_stage(2, 2);
    asm volatile("cp.async.wait_group 2;" ::: "memory");
    __syncthreads();

    uint32_t ah[4][4], bh[2][4];     // current-sub hi frags (rotating)
    uint32_t ah2[4][4], bh2[2][4];   // next-sub hi frags
    uint32_t al[4][4], bl[2][4];

    ldA(smb, chi0, ah);
    ldB(smb, chi0, bh);

    int cs = 0;
    #pragma unroll 1
    for (int c = 0; c < NK; c++) {
        const uint32_t st = smb + (uint32_t)cs * STAGE;
        const int ns = (cs + 1 == NSTAGE) ? 0 : cs + 1;
        const uint32_t stn = smb + (uint32_t)ns * STAGE;

        // ---- sub 0 ----
        ldA(st, clo0, al);
        ldB(st, clo0, bl);
        mmaT(ah, bh);                 // t1: hi*hi
        mmaT(ah, bl);                 // t3: hi*lo  (ah dies)
        ldA(st, chi1, ah2);           // prefetch sub1 hi A
        mmaT(al, bh);                 // t2: lo*hi  (al, bh die)
        ldB(st, chi1, bh2);           // prefetch sub1 hi B

        // ---- sub 1 ----
        ldA(st, clo1, al);
        ldB(st, clo1, bl);
        mmaT(ah2, bh2);               // t1
        mmaT(ah2, bl);                // t3  (ah2 dies)
        asm volatile("cp.async.wait_group 1;" ::: "memory");
        __syncthreads();
        load_stage(c + 3, cs);        // refill the stage just consumed
        if (c + 1 < NK) ldA(stn, chi0, ah);   // prefetch next chunk sub0
        mmaT(al, bh2);                // t2 (register-only, hides barrier)
        if (c + 1 < NK) ldB(stn, chi0, bh);

        cs = ns;
    }
    __syncthreads();

    // ---- epilogue ----
    #pragma unroll
    for (int m = 0; m < 4; m++) {
        const size_t rG = rowGlob0 + warp_m * 64 + m * 16 + (lid >> 2);
        #pragma unroll
        for (int n = 0; n < 4; n++) {
            const int cl = warp_n * 32 + n * 8 + (lid & 3) * 2;
            const float b0 = s_bias[cl], b1 = s_bias[cl + 1];
            const int cg = colBase + cl;
            #pragma unroll
            for (int h = 0; h < 2; h++) {
                float v0 = acc[m][n][2 * h + 0] + b0;
                float v1 = acc[m][n][2 * h + 1] + b1;
                const size_t rr = rG + h * 8;
                if (EPI == 1) {
                    v0 = gelu_exact(v0); v1 = gelu_exact(v1);
                    __nv_bfloat16 h0, l0, h1, l1;
                    split_bf16(v0, h0, l0); split_bf16(v1, h1, l1);
                    __nv_bfloat16* orow = OutH + rr * (size_t)(2 * NBtot)
                                        + (size_t)(cg >> 5) * 64 + (cg & 31);
                    *(uint32_t*)orow        = pk(h0, h1);
                    *(uint32_t*)(orow + 32) = pk(l0, l1);
                } else {
                    *(float2*)(OutF + rr * (size_t)NBtot + cg) = make_float2(v0, v1);
                }
            }
        }
    }
}

// ============================================================================
extern "C" void kernel_launch(void* const* d_in, const int* in_sizes, int n_in,
                              void* d_out, int out_size)
{
    (void)in_sizes; (void)n_in; (void)out_size;
    const float* x  = (const float*)d_in[0];
    const float* w1 = (const float*)d_in[1];
    const float* b1 = (const float*)d_in[2];
    const float* w2 = (const float*)d_in[3];
    const float* b2 = (const float*)d_in[4];
    float* out = (float*)d_out;

    __nv_bfloat16 *x2, *w1t2, *h2, *w2t2;
    cudaGetSymbolAddress((void**)&x2,   g_x2);
    cudaGetSymbolAddress((void**)&w1t2, g_w1t2);
    cudaGetSymbolAddress((void**)&h2,   g_h2);
    cudaGetSymbolAddress((void**)&w2t2, g_w2t2);

    const int SMEM = NSTAGE * STAGE;   // 98304
    cudaFuncSetAttribute(gemm_mma<1>, cudaFuncAttributeMaxDynamicSharedMemorySize, SMEM);
    cudaFuncSetAttribute(gemm_mma<0>, cudaFuncAttributeMaxDynamicSharedMemorySize, SMEM);

    convert_x<<<32768, 256>>>(x, x2);
    convert_w<<<dim3(H_ / 32, D_ / 32, E_), dim3(32, 8)>>>(w1, w1t2, D_, H_);
    convert_w<<<dim3(D_ / 32, H_ / 32, E_), dim3(32, 8)>>>(w2, w2t2, H_, D_);

    gemm_mma<1><<<dim3(H_ / 128, T_ / 128, E_), 256, SMEM>>>(
        x2, w1t2, b1, nullptr, h2, D_, H_);

    gemm_mma<0><<<dim3(D_ / 128, T_ / 128, E_), 256, SMEM>>>(
        h2, w2t2, b2, out, nullptr, H_, D_);
}

// round 6
// speedup vs baseline: 2.7537x; 1.0670x over previous
#include <cuda_runtime.h>
#include <cuda_bf16.h>
#include <cstdint>
#include <math.h>

// ============================================================================
// Experts MLP via mma.sync bf16 split-compensation, term-fused form.
// Rows chunked [hi(32) | lo(32)] bf16 = 128B per k32 chunk.
// R6: compile-time K (template), register-rotated stage bases, peeled last
// chunk, running global pointers -> minimal per-chunk ALU work.
// ============================================================================

#define E_ 8
#define T_ 4096
#define D_ 1024
#define H_ 2048

#define A_BYTES 16384              // 128 rows * 128B
#define STAGE   32768              // A + B tile
#define NSTAGE  3

__device__ __align__(256) __nv_bfloat16 g_x2[(size_t)32768 * 2048];
__device__ __align__(256) __nv_bfloat16 g_w1t2[(size_t)8 * 2048 * 2048];
__device__ __align__(256) __nv_bfloat16 g_h2[(size_t)32768 * 4096];
__device__ __align__(256) __nv_bfloat16 g_w2t2[(size_t)8 * 1024 * 4096];

__device__ __forceinline__ uint32_t smem_u32(const void* p) {
    uint32_t a;
    asm("{ .reg .u64 t; cvta.to.shared.u64 t, %1; cvt.u32.u64 %0, t; }"
        : "=r"(a) : "l"(p));
    return a;
}
__device__ __forceinline__ void cpa16(uint32_t dst, const void* src) {
    asm volatile("cp.async.cg.shared.global [%0], [%1], 16;" :: "r"(dst), "l"(src));
}
__device__ __forceinline__ void ldsm_x4(uint32_t* r, uint32_t addr) {
    asm volatile("ldmatrix.sync.aligned.m8n8.x4.shared.b16 {%0,%1,%2,%3}, [%4];"
                 : "=r"(r[0]), "=r"(r[1]), "=r"(r[2]), "=r"(r[3]) : "r"(addr));
}
__device__ __forceinline__ void mma_bf16(float* c, const uint32_t* a,
                                         uint32_t b0, uint32_t b1) {
    asm volatile(
        "mma.sync.aligned.m16n8k16.row.col.f32.bf16.bf16.f32 "
        "{%0,%1,%2,%3}, {%4,%5,%6,%7}, {%8,%9}, {%0,%1,%2,%3};"
        : "+f"(c[0]), "+f"(c[1]), "+f"(c[2]), "+f"(c[3])
        : "r"(a[0]), "r"(a[1]), "r"(a[2]), "r"(a[3]), "r"(b0), "r"(b1));
}

__device__ __forceinline__ float gelu_exact(float x) {
    return 0.5f * x * (1.0f + erff(x * 0.70710678118654752f));
}
__device__ __forceinline__ void split_bf16(float v, __nv_bfloat16& h, __nv_bfloat16& l) {
    h = __float2bfloat16_rn(v);
    l = __float2bfloat16_rn(v - __bfloat162float(h));
}
__device__ __forceinline__ uint32_t pk(__nv_bfloat16 a, __nv_bfloat16 b) {
    return (uint32_t)__bfloat16_as_ushort(a) | ((uint32_t)__bfloat16_as_ushort(b) << 16);
}

// ============================================================================
// prepasses
// ============================================================================
__global__ void convert_x(const float* __restrict__ x, __nv_bfloat16* __restrict__ x2) {
    size_t gid = (size_t)blockIdx.x * 256 + threadIdx.x;
    size_t base = gid * 4;
    size_t row = base >> 10;
    int c = (int)(base & 1023);
    float4 v = *(const float4*)(x + base);
    __nv_bfloat16 h0, h1, h2, h3, l0, l1, l2, l3;
    split_bf16(v.x, h0, l0); split_bf16(v.y, h1, l1);
    split_bf16(v.z, h2, l2); split_bf16(v.w, h3, l3);
    __nv_bfloat16* orow = x2 + row * 2048 + (size_t)(c >> 5) * 64 + (c & 31);
    *(uint2*)orow        = make_uint2(pk(h0, h1), pk(h2, h3));
    *(uint2*)(orow + 32) = make_uint2(pk(l0, l1), pk(l2, l3));
}

__global__ void convert_w(const float* __restrict__ w, __nv_bfloat16* __restrict__ wt2,
                          int K, int N) {
    __shared__ float t[32][33];
    const int e = blockIdx.z;
    const int nb = blockIdx.x * 32, kb = blockIdx.y * 32;
    const float* we = w + (size_t)e * K * N;
    __nv_bfloat16* oe = wt2 + (size_t)e * N * 2 * K;
    const int tx = threadIdx.x, ty = threadIdx.y; // (32, 8)
    #pragma unroll
    for (int i = 0; i < 4; i++)
        t[ty + 8 * i][tx] = we[(size_t)(kb + ty + 8 * i) * N + nb + tx];
    __syncthreads();
    #pragma unroll
    for (int i = 0; i < 4; i++) {
        int n = nb + ty + 8 * i, k = kb + tx;
        float v = t[tx][ty + 8 * i];
        __nv_bfloat16 h, l;
        split_bf16(v, h, l);
        __nv_bfloat16* r = oe + (size_t)n * 2 * K + (size_t)(k >> 5) * 64 + (k & 31);
        r[0] = h; r[32] = l;
    }
}

// ============================================================================
// GEMM: C tile 128x128; 3-term split MMA, 3-stage cp.async, compile-time K.
// ============================================================================
template <int EPI, int KR>
__global__ __launch_bounds__(256, 2)
void gemm_mma(const __nv_bfloat16* __restrict__ A,
              const __nv_bfloat16* __restrict__ B,
              const float* __restrict__ bias,
              float* __restrict__ OutF,
              __nv_bfloat16* __restrict__ OutH,
              int NBtot)
{
    extern __shared__ __align__(1024) char sm[];
    __shared__ float s_bias[128];

    constexpr int NK = KR / 32;
    constexpr size_t rowLen = (size_t)2 * KR;      // bf16 per row
    constexpr size_t gStride = 32 * rowLen * 2;    // bytes between seg rows

    const int tid = threadIdx.x;
    const int wid = tid >> 5;
    const int lid = tid & 31;
    const int warp_m = wid >> 2;
    const int warp_n = wid & 3;
    const int e = blockIdx.z;
    const int rowBase = blockIdx.y * 128;
    const int colBase = blockIdx.x * 128;
    const size_t rowGlob0 = (size_t)e * T_ + rowBase;
    const uint32_t smb = smem_u32(sm);

    if (tid < 128) s_bias[tid] = bias[(size_t)e * NBtot + colBase + tid];

    // cp.async running pointers (advance 128B per chunk)
    const int r0 = tid >> 3, g0 = tid & 7;
    const char* aCur = (const char*)(A + (rowGlob0 + r0) * rowLen) + g0 * 16;
    const char* bCur = (const char*)(B + ((size_t)e * NBtot + colBase + r0) * rowLen) + g0 * 16;
    const uint32_t sO0 = (uint32_t)(r0 * 128 + ((g0 << 4) ^ ((r0 & 7) << 4)));

    // ldmatrix addressing
    const int lr = (lid & 7) + ((lid >> 3) & 1) * 8;
    const uint32_t lcol = ((lid >> 4) & 1) << 4;
    const uint32_t xr = (uint32_t)(lr & 7) << 4;
    const uint32_t arb0 = (uint32_t)(warp_m * 64 + lr) * 128;
    const uint32_t brb0 = (uint32_t)(warp_n * 32 + lr) * 128 + A_BYTES;

    const uint32_t chi0 = lcol ^ xr;
    const uint32_t chi1 = (32u | lcol) ^ xr;
    const uint32_t clo0 = chi0 ^ 64u;
    const uint32_t clo1 = chi1 ^ 64u;

    float acc[4][4][4];
    #pragma unroll
    for (int m = 0; m < 4; m++)
        #pragma unroll
        for (int n = 0; n < 4; n++)
            #pragma unroll
            for (int q = 0; q < 4; q++)
                acc[m][n][q] = 0.0f;

    auto fill = [&](uint32_t sbase) {    // issue 8 cp.async from running ptrs
        uint32_t sb = sbase + sO0;
        #pragma unroll
        for (int i = 0; i < 4; i++)
            cpa16(sb + i * 4096, aCur + i * gStride);
        #pragma unroll
        for (int i = 0; i < 4; i++)
            cpa16(sb + A_BYTES + i * 4096, bCur + i * gStride);
        asm volatile("cp.async.commit_group;" ::: "memory");
        aCur += 128; bCur += 128;
    };
    auto commit_empty = [&]() {
        asm volatile("cp.async.commit_group;" ::: "memory");
    };

    auto ldA = [&](uint32_t st, uint32_t col, uint32_t (&fr)[4][4]) {
        #pragma unroll
        for (int f = 0; f < 4; f++)
            ldsm_x4(fr[f], st + arb0 + f * 2048 + col);
    };
    auto ldB = [&](uint32_t st, uint32_t col, uint32_t (&fr)[2][4]) {
        #pragma unroll
        for (int g = 0; g < 2; g++)
            ldsm_x4(fr[g], st + brb0 + g * 2048 + col);
    };
    auto mmaT = [&](const uint32_t (&a)[4][4], const uint32_t (&b)[2][4]) {
        #pragma unroll
        for (int m = 0; m < 4; m++)
            #pragma unroll
            for (int n = 0; n < 4; n++)
                mma_bf16(acc[m][n], a[m], b[n >> 1][n & 1], b[n >> 1][2 + (n & 1)]);
    };

    // prologue: fill 3 stages
    uint32_t st0 = smb, st1 = smb + STAGE, st2 = smb + 2 * STAGE;
    fill(st0); fill(st1); fill(st2);
    asm volatile("cp.async.wait_group 2;" ::: "memory");
    __syncthreads();

    uint32_t ah[4][4], bh[2][4];
    uint32_t ah2[4][4], bh2[2][4];
    uint32_t al[4][4], bl[2][4];

    ldA(st0, chi0, ah);
    ldB(st0, chi0, bh);

    #pragma unroll 1
    for (int c = 0; c < NK - 1; c++) {
        const uint32_t st = st0;

        // ---- sub 0 ----
        ldA(st, clo0, al);
        ldB(st, clo0, bl);
        mmaT(ah, bh);                 // t1: hi*hi
        mmaT(ah, bl);                 // t3: hi*lo  (ah dies)
        ldA(st, chi1, ah2);
        mmaT(al, bh);                 // t2: lo*hi
        ldB(st, chi1, bh2);

        // ---- sub 1 ----
        ldA(st, clo1, al);
        ldB(st, clo1, bl);
        mmaT(ah2, bh2);
        mmaT(ah2, bl);
        asm volatile("cp.async.wait_group 1;" ::: "memory");
        __syncthreads();
        if (c + 3 < NK) fill(st); else commit_empty();
        ldA(st1, chi0, ah);           // next chunk sub0 prefetch
        mmaT(al, bh2);                // register-only, hides barrier
        ldB(st1, chi0, bh);

        // rotate stages
        uint32_t t = st0; st0 = st1; st1 = st2; st2 = t;
    }

    // ---- final chunk (no next prefetch, no refill) ----
    {
        const uint32_t st = st0;
        ldA(st, clo0, al);
        ldB(st, clo0, bl);
        mmaT(ah, bh);
        mmaT(ah, bl);
        ldA(st, chi1, ah2);
        mmaT(al, bh);
        ldB(st, chi1, bh2);

        ldA(st, clo1, al);
        ldB(st, clo1, bl);
        mmaT(ah2, bh2);
        mmaT(ah2, bl);
        mmaT(al, bh2);
    }
    __syncthreads();

    // ---- epilogue ----
    #pragma unroll
    for (int m = 0; m < 4; m++) {
        const size_t rG = rowGlob0 + warp_m * 64 + m * 16 + (lid >> 2);
        #pragma unroll
        for (int n = 0; n < 4; n++) {
            const int cl = warp_n * 32 + n * 8 + (lid & 3) * 2;
            const float b0 = s_bias[cl], b1 = s_bias[cl + 1];
            const int cg = colBase + cl;
            #pragma unroll
            for (int h = 0; h < 2; h++) {
                float v0 = acc[m][n][2 * h + 0] + b0;
                float v1 = acc[m][n][2 * h + 1] + b1;
                const size_t rr = rG + h * 8;
                if (EPI == 1) {
                    v0 = gelu_exact(v0); v1 = gelu_exact(v1);
                    __nv_bfloat16 h0, l0, h1, l1;
                    split_bf16(v0, h0, l0); split_bf16(v1, h1, l1);
                    __nv_bfloat16* orow = OutH + rr * (size_t)(2 * NBtot)
                                        + (size_t)(cg >> 5) * 64 + (cg & 31);
                    *(uint32_t*)orow        = pk(h0, h1);
                    *(uint32_t*)(orow + 32) = pk(l0, l1);
                } else {
                    *(float2*)(OutF + rr * (size_t)NBtot + cg) = make_float2(v0, v1);
                }
            }
        }
    }
}

// ============================================================================
extern "C" void kernel_launch(void* const* d_in, const int* in_sizes, int n_in,
                              void* d_out, int out_size)
{
    (void)in_sizes; (void)n_in; (void)out_size;
    const float* x  = (const float*)d_in[0];
    const float* w1 = (const float*)d_in[1];
    const float* b1 = (const float*)d_in[2];
    const float* w2 = (const float*)d_in[3];
    const float* b2 = (const float*)d_in[4];
    float* out = (float*)d_out;

    __nv_bfloat16 *x2, *w1t2, *h2, *w2t2;
    cudaGetSymbolAddress((void**)&x2,   g_x2);
    cudaGetSymbolAddress((void**)&w1t2, g_w1t2);
    cudaGetSymbolAddress((void**)&h2,   g_h2);
    cudaGetSymbolAddress((void**)&w2t2, g_w2t2);

    const int SMEM = NSTAGE * STAGE;   // 98304
    cudaFuncSetAttribute((const void*)gemm_mma<1, D_>,
                         cudaFuncAttributeMaxDynamicSharedMemorySize, SMEM);
    cudaFuncSetAttribute((const void*)gemm_mma<0, H_>,
                         cudaFuncAttributeMaxDynamicSharedMemorySize, SMEM);

    convert_x<<<32768, 256>>>(x, x2);
    convert_w<<<dim3(H_ / 32, D_ / 32, E_), dim3(32, 8)>>>(w1, w1t2, D_, H_);
    convert_w<<<dim3(D_ / 32, H_ / 32, E_), dim3(32, 8)>>>(w2, w2t2, H_, D_);

    gemm_mma<1, D_><<<dim3(H_ / 128, T_ / 128, E_), 256, SMEM>>>(
        x2, w1t2, b1, nullptr, h2, H_);

    gemm_mma<0, H_><<<dim3(D_ / 128, T_ / 128, E_), 256, SMEM>>>(
        h2, w2t2, b2, out, nullptr, D_);
}

// round 7
// speedup vs baseline: 3.4179x; 1.2412x over previous
#include <cuda_runtime.h>
#include <cuda_fp16.h>
#include <cstdint>
#include <math.h>

// ============================================================================
// Experts MLP via mma.sync fp16 2-term split GEMMs.
//   A operands kept as fp16 (hi,lo) pairs -> A is exact to 2^-22.
//   B operands rounded once to fp16 (hi only).
//   A@B ~= hiA@hiB + loA@hiB  (= A_exact @ fp16(B)); error ~2e-4 RMS per GEMM.
// Layouts:
//   x2  [32768][2048 fp16]  rows chunked per k32: [hi32|lo32] (128B chunks)
//   w1t [e][n][1024 fp16]   plain K-major transpose (hi only)
//   h2  [32768][4096 fp16]  chunked split (epilogue of GEMM1)
//   w2t [e][n][2048 fp16]
// GEMM: 128x128 CTA tile, 8 warps (64x32 each), 4-stage cp.async,
//       one __syncthreads per TWO k32 chunks (stage-pair ping-pong).
// ============================================================================

#define E_ 8
#define T_ 4096
#define D_ 1024
#define H_ 2048

#define BOFF  16384                 // B region offset inside a stage
#define SSZ   26624                 // stage: A 16384 + B 128*80
#define NSTG  4

__device__ __align__(256) __half g_x2[(size_t)32768 * 2048];        // 128MB
__device__ __align__(256) __half g_w1t[(size_t)8 * 2048 * 1024];    //  32MB
__device__ __align__(256) __half g_h2[(size_t)32768 * 4096];        // 256MB
__device__ __align__(256) __half g_w2t[(size_t)8 * 1024 * 2048];    //  32MB

__device__ __forceinline__ uint32_t smem_u32(const void* p) {
    uint32_t a;
    asm("{ .reg .u64 t; cvta.to.shared.u64 t, %1; cvt.u32.u64 %0, t; }"
        : "=r"(a) : "l"(p));
    return a;
}
__device__ __forceinline__ void cpa16(uint32_t dst, const void* src) {
    asm volatile("cp.async.cg.shared.global [%0], [%1], 16;" :: "r"(dst), "l"(src));
}
__device__ __forceinline__ void ldsm_x4(uint32_t* r, uint32_t addr) {
    asm volatile("ldmatrix.sync.aligned.m8n8.x4.shared.b16 {%0,%1,%2,%3}, [%4];"
                 : "=r"(r[0]), "=r"(r[1]), "=r"(r[2]), "=r"(r[3]) : "r"(addr));
}
__device__ __forceinline__ void mma_f16(float* c, const uint32_t* a,
                                        uint32_t b0, uint32_t b1) {
    asm volatile(
        "mma.sync.aligned.m16n8k16.row.col.f32.f16.f16.f32 "
        "{%0,%1,%2,%3}, {%4,%5,%6,%7}, {%8,%9}, {%0,%1,%2,%3};"
        : "+f"(c[0]), "+f"(c[1]), "+f"(c[2]), "+f"(c[3])
        : "r"(a[0]), "r"(a[1]), "r"(a[2]), "r"(a[3]), "r"(b0), "r"(b1));
}

__device__ __forceinline__ float gelu_exact(float x) {
    return 0.5f * x * (1.0f + erff(x * 0.70710678118654752f));
}
__device__ __forceinline__ void split_f16(float v, __half& h, __half& l) {
    h = __float2half_rn(v);
    l = __float2half_rn(v - __half2float(h));
}
__device__ __forceinline__ uint32_t pk(__half a, __half b) {
    return (uint32_t)__half_as_ushort(a) | ((uint32_t)__half_as_ushort(b) << 16);
}

// ============================================================================
// prepasses
// ============================================================================
// x row [1024 fp32] -> x2 row [2048 fp16] chunked [hi32|lo32]
__global__ void convert_x(const float* __restrict__ x, __half* __restrict__ x2) {
    size_t gid = (size_t)blockIdx.x * 256 + threadIdx.x;
    size_t base = gid * 4;
    size_t row = base >> 10;
    int c = (int)(base & 1023);
    float4 v = *(const float4*)(x + base);
    __half h0, h1, h2, h3, l0, l1, l2, l3;
    split_f16(v.x, h0, l0); split_f16(v.y, h1, l1);
    split_f16(v.z, h2, l2); split_f16(v.w, h3, l3);
    __half* orow = x2 + row * 2048 + (size_t)(c >> 5) * 64 + (c & 31);
    *(uint2*)orow        = make_uint2(pk(h0, h1), pk(h2, h3));
    *(uint2*)(orow + 32) = make_uint2(pk(l0, l1), pk(l2, l3));
}

// w [E,K,N] fp32 -> wt [E,N,K] fp16 (hi only, plain K-major)
__global__ void convert_w(const float* __restrict__ w, __half* __restrict__ wt,
                          int K, int N) {
    __shared__ float t[32][33];
    const int e = blockIdx.z;
    const int nb = blockIdx.x * 32, kb = blockIdx.y * 32;
    const float* we = w + (size_t)e * K * N;
    __half* oe = wt + (size_t)e * N * K;
    const int tx = threadIdx.x, ty = threadIdx.y; // (32, 8)
    #pragma unroll
    for (int i = 0; i < 4; i++)
        t[ty + 8 * i][tx] = we[(size_t)(kb + ty + 8 * i) * N + nb + tx];
    __syncthreads();
    #pragma unroll
    for (int i = 0; i < 4; i++) {
        int n = nb + ty + 8 * i, k = kb + tx;
        oe[(size_t)n * K + k] = __float2half_rn(t[tx][ty + 8 * i]);
    }
}

// ============================================================================
// GEMM: C tile 128x128; 2-term fp16 split, 4-stage cp.async, sync per 2 chunks.
// ============================================================================
template <int EPI, int KR>
__global__ __launch_bounds__(256, 2)
void gemm_mma(const __half* __restrict__ A,
              const __half* __restrict__ B,
              const float* __restrict__ bias,
              float* __restrict__ OutF,
              __half* __restrict__ OutH,
              int NBtot)
{
    extern __shared__ __align__(1024) char sm[];
    __shared__ float s_bias[128];

    constexpr int NK = KR / 32;           // k32 chunks
    constexpr int NP = NK / 2;            // pairs
    constexpr size_t gStride = (size_t)128 * KR;  // bytes: A 32 rows / B 64 rows

    const int tid = threadIdx.x;
    const int wid = tid >> 5;
    const int lid = tid & 31;
    const int warp_m = wid >> 2;
    const int warp_n = wid & 3;
    const int e = blockIdx.z;
    const int rowBase = blockIdx.y * 128;
    const int colBase = blockIdx.x * 128;
    const size_t rowGlob0 = (size_t)e * T_ + rowBase;
    const uint32_t smb = smem_u32(sm);

    if (tid < 128) s_bias[tid] = bias[(size_t)e * NBtot + colBase + tid];

    // ---- cp.async running pointers ----
    // A: 1024 segs of 16B (128 rows x 8); 4/thread. rows r = tid>>3 + 32i.
    const int rA = tid >> 3, gA = tid & 7;
    const char* aCur = (const char*)(A + (rowGlob0 + rA) * (size_t)(2 * KR)) + gA * 16;
    const uint32_t aO = (uint32_t)(rA * 128 + ((gA << 4) ^ ((rA & 7) << 4)));
    // B: 512 segs of 16B (128 rows x 4); 2/thread. rows r = tid>>2 + 64i.
    const int rB = tid >> 2, gB = tid & 3;
    const char* bCur = (const char*)(B + ((size_t)e * NBtot + colBase + rB) * (size_t)KR) + gB * 16;
    const uint32_t bO = (uint32_t)(BOFF + rB * 80 + gB * 16);

    // ---- ldmatrix addressing ----
    const int lr = (lid & 7) + ((lid >> 3) & 1) * 8;
    const uint32_t lcol = ((lid >> 4) & 1) << 4;
    const uint32_t xr = (uint32_t)(lr & 7) << 4;
    const uint32_t arb0 = (uint32_t)(warp_m * 64 + lr) * 128;
    const uint32_t brb0 = (uint32_t)(BOFF + (warp_n * 32 + lr) * 80);

    const uint32_t chi0 = lcol ^ xr;           // A hi, sub0
    const uint32_t chi1 = (32u | lcol) ^ xr;   // A hi, sub1
    const uint32_t clo0 = chi0 ^ 64u;          // A lo, sub0
    const uint32_t clo1 = chi1 ^ 64u;          // A lo, sub1
    const uint32_t bc0 = lcol;                 // B sub0
    const uint32_t bc1 = 32u + lcol;           // B sub1

    float acc[4][4][4];
    #pragma unroll
    for (int m = 0; m < 4; m++)
        #pragma unroll
        for (int n = 0; n < 4; n++)
            #pragma unroll
            for (int q = 0; q < 4; q++)
                acc[m][n][q] = 0.0f;

    auto fill = [&](uint32_t sb) {   // one chunk into stage at sb
        #pragma unroll
        for (int i = 0; i < 4; i++)
            cpa16(sb + aO + i * 4096, aCur + i * gStride);
        #pragma unroll
        for (int i = 0; i < 2; i++)
            cpa16(sb + bO + i * 5120, bCur + i * gStride);
        asm volatile("cp.async.commit_group;" ::: "memory");
        aCur += 128; bCur += 64;
    };

    auto ldA = [&](uint32_t st, uint32_t col, uint32_t (&fr)[4][4]) {
        #pragma unroll
        for (int f = 0; f < 4; f++)
            ldsm_x4(fr[f], st + arb0 + f * 2048 + col);
    };
    auto ldB = [&](uint32_t st, uint32_t col, uint32_t (&fr)[2][4]) {
        #pragma unroll
        for (int g = 0; g < 2; g++)
            ldsm_x4(fr[g], st + brb0 + g * 1280 + col);
    };
    auto mmaT = [&](const uint32_t (&a)[4][4], const uint32_t (&b)[2][4]) {
        #pragma unroll
        for (int m = 0; m < 4; m++)
            #pragma unroll
            for (int n = 0; n < 4; n++)
                mma_f16(acc[m][n], a[m], b[n >> 1][n & 1], b[n >> 1][2 + (n & 1)]);
    };

    // prologue: fill pair 0 (chunks 0,1)
    fill(smb);
    fill(smb + SSZ);

    uint32_t ah[4][4], ah2[4][4], al[4][4];
    uint32_t bh[2][4], bh2[2][4];

    #pragma unroll 1
    for (int p = 0; p < NP; p++) {
        asm volatile("cp.async.wait_group 0;" ::: "memory");
        __syncthreads();
        const uint32_t sa = smb + (uint32_t)((p & 1) ? 2 * SSZ : 0);
        const uint32_t sb2 = sa + SSZ;

        ldA(sa, chi0, ah);
        ldB(sa, bc0, bh);
        if (p + 1 < NP) {                       // prefetch next pair
            const uint32_t oa = smb + (uint32_t)((p & 1) ? 0 : 2 * SSZ);
            fill(oa);
            fill(oa + SSZ);
        }

        // ---- chunk a ----
        ldA(sa, clo0, al);
        mmaT(ah, bh);                 // hi*hi  sub0
        ldA(sa, chi1, ah2);
        mmaT(al, bh);                 // lo*hi  sub0
        ldB(sa, bc1, bh2);

        ldA(sa, clo1, al);
        mmaT(ah2, bh2);               // sub1
        ldA(sb2, chi0, ah);
        mmaT(al, bh2);
        ldB(sb2, bc0, bh);

        // ---- chunk b ----
        ldA(sb2, clo0, al);
        mmaT(ah, bh);
        ldA(sb2, chi1, ah2);
        mmaT(al, bh);
        ldB(sb2, bc1, bh2);

        ldA(sb2, clo1, al);
        mmaT(ah2, bh2);
        mmaT(al, bh2);
    }
    __syncthreads();

    // ---- epilogue ----
    #pragma unroll
    for (int m = 0; m < 4; m++) {
        const size_t rG = rowGlob0 + warp_m * 64 + m * 16 + (lid >> 2);
        #pragma unroll
        for (int n = 0; n < 4; n++) {
            const int cl = warp_n * 32 + n * 8 + (lid & 3) * 2;
            const float b0 = s_bias[cl], b1 = s_bias[cl + 1];
            const int cg = colBase + cl;
            #pragma unroll
            for (int h = 0; h < 2; h++) {
                float v0 = acc[m][n][2 * h + 0] + b0;
                float v1 = acc[m][n][2 * h + 1] + b1;
                const size_t rr = rG + h * 8;
                if (EPI == 1) {
                    v0 = gelu_exact(v0); v1 = gelu_exact(v1);
                    __half h0, l0, h1, l1;
                    split_f16(v0, h0, l0); split_f16(v1, h1, l1);
                    __half* orow = OutH + rr * (size_t)(2 * NBtot)
                                 + (size_t)(cg >> 5) * 64 + (cg & 31);
                    *(uint32_t*)orow        = pk(h0, h1);
                    *(uint32_t*)(orow + 32) = pk(l0, l1);
                } else {
                    *(float2*)(OutF + rr * (size_t)NBtot + cg) = make_float2(v0, v1);
                }
            }
        }
    }
}

// ============================================================================
extern "C" void kernel_launch(void* const* d_in, const int* in_sizes, int n_in,
                              void* d_out, int out_size)
{
    (void)in_sizes; (void)n_in; (void)out_size;
    const float* x  = (const float*)d_in[0];
    const float* w1 = (const float*)d_in[1];
    const float* b1 = (const float*)d_in[2];
    const float* w2 = (const float*)d_in[3];
    const float* b2 = (const float*)d_in[4];
    float* out = (float*)d_out;

    __half *x2, *w1t, *h2, *w2t;
    cudaGetSymbolAddress((void**)&x2,  g_x2);
    cudaGetSymbolAddress((void**)&w1t, g_w1t);
    cudaGetSymbolAddress((void**)&h2,  g_h2);
    cudaGetSymbolAddress((void**)&w2t, g_w2t);

    const int SMEM = NSTG * SSZ;    // 106496
    cudaFuncSetAttribute((const void*)gemm_mma<1, D_>,
                         cudaFuncAttributeMaxDynamicSharedMemorySize, SMEM);
    cudaFuncSetAttribute((const void*)gemm_mma<0, H_>,
                         cudaFuncAttributeMaxDynamicSharedMemorySize, SMEM);

    convert_x<<<32768, 256>>>(x, x2);
    convert_w<<<dim3(H_ / 32, D_ / 32, E_), dim3(32, 8)>>>(w1, w1t, D_, H_);
    convert_w<<<dim3(D_ / 32, H_ / 32, E_), dim3(32, 8)>>>(w2, w2t, H_, D_);

    // GEMM1: K=1024 -> h2 (split fp16) with bias+GELU
    gemm_mma<1, D_><<<dim3(H_ / 128, T_ / 128, E_), 256, SMEM>>>(
        x2, w1t, b1, nullptr, h2, H_);

    // GEMM2: K=2048 -> fp32 out with bias
    gemm_mma<0, H_><<<dim3(D_ / 128, T_ / 128, E_), 256, SMEM>>>(
        h2, w2t, b2, out, nullptr, D_);
}

// round 8
// speedup vs baseline: 7.1979x; 2.1059x over previous
#include <cuda_runtime.h>
#include <cuda_fp16.h>
#include <cstdint>
#include <math.h>

// ============================================================================
// Experts MLP via plain fp16 mma.sync GEMMs (fp32 accumulate).
// Error budget: 4 fp16 roundings (x, w1, h, w2) ~= 4.2e-4 rel << 1e-3.
//   x  -> x2  [32768][1024 fp16]
//   w1 -> w1t [e][n][1024 fp16]   (K-major transpose)
//   GEMM1: acc = x2 @ w1t^T (fp32) + b1, exact GELU -> h2 fp16
//   w2 -> w2t [e][n][2048 fp16]
//   GEMM2: acc = h2 @ w2t^T (fp32) + b2 -> fp32 out
// GEMM: 128x128 CTA tile, 8 warps (64x32), k64 chunks (128B SW128 rows),
//       3-stage cp.async, one __syncthreads per k64 chunk.
// ============================================================================

#define E_ 8
#define T_ 4096
#define D_ 1024
#define H_ 2048

#define A_BYTES 16384              // 128 rows * 128B
#define STAGE   32768              // A + B tile
#define NSTAGE  3

__device__ __align__(256) __half g_x2[(size_t)32768 * 1024];       //  64MB
__device__ __align__(256) __half g_w1t[(size_t)8 * 2048 * 1024];   //  32MB
__device__ __align__(256) __half g_h2[(size_t)32768 * 2048];       // 128MB
__device__ __align__(256) __half g_w2t[(size_t)8 * 1024 * 2048];   //  32MB

__device__ __forceinline__ uint32_t smem_u32(const void* p) {
    uint32_t a;
    asm("{ .reg .u64 t; cvta.to.shared.u64 t, %1; cvt.u32.u64 %0, t; }"
        : "=r"(a) : "l"(p));
    return a;
}
__device__ __forceinline__ void cpa16(uint32_t dst, const void* src) {
    asm volatile("cp.async.cg.shared.global [%0], [%1], 16;" :: "r"(dst), "l"(src));
}
__device__ __forceinline__ void ldsm_x4(uint32_t* r, uint32_t addr) {
    asm volatile("ldmatrix.sync.aligned.m8n8.x4.shared.b16 {%0,%1,%2,%3}, [%4];"
                 : "=r"(r[0]), "=r"(r[1]), "=r"(r[2]), "=r"(r[3]) : "r"(addr));
}
__device__ __forceinline__ void mma_f16(float* c, const uint32_t* a,
                                        uint32_t b0, uint32_t b1) {
    asm volatile(
        "mma.sync.aligned.m16n8k16.row.col.f32.f16.f16.f32 "
        "{%0,%1,%2,%3}, {%4,%5,%6,%7}, {%8,%9}, {%0,%1,%2,%3};"
        : "+f"(c[0]), "+f"(c[1]), "+f"(c[2]), "+f"(c[3])
        : "r"(a[0]), "r"(a[1]), "r"(a[2]), "r"(a[3]), "r"(b0), "r"(b1));
}

__device__ __forceinline__ float gelu_exact(float x) {
    return 0.5f * x * (1.0f + erff(x * 0.70710678118654752f));
}
__device__ __forceinline__ uint32_t pk(__half a, __half b) {
    return (uint32_t)__half_as_ushort(a) | ((uint32_t)__half_as_ushort(b) << 16);
}

// ============================================================================
// prepasses
// ============================================================================
__global__ void convert_x(const float* __restrict__ x, __half* __restrict__ x2) {
    size_t base = ((size_t)blockIdx.x * 256 + threadIdx.x) * 4;
    float4 v = *(const float4*)(x + base);
    uint2 o = make_uint2(pk(__float2half_rn(v.x), __float2half_rn(v.y)),
                         pk(__float2half_rn(v.z), __float2half_rn(v.w)));
    *(uint2*)(x2 + base) = o;
}

// w [E,K,N] fp32 -> wt [E,N,K] fp16
__global__ void convert_w(const float* __restrict__ w, __half* __restrict__ wt,
                          int K, int N) {
    __shared__ float t[32][33];
    const int e = blockIdx.z;
    const int nb = blockIdx.x * 32, kb = blockIdx.y * 32;
    const float* we = w + (size_t)e * K * N;
    __half* oe = wt + (size_t)e * N * K;
    const int tx = threadIdx.x, ty = threadIdx.y; // (32, 8)
    #pragma unroll
    for (int i = 0; i < 4; i++)
        t[ty + 8 * i][tx] = we[(size_t)(kb + ty + 8 * i) * N + nb + tx];
    __syncthreads();
    #pragma unroll
    for (int i = 0; i < 4; i++) {
        int n = nb + ty + 8 * i, k = kb + tx;
        oe[(size_t)n * K + k] = __float2half_rn(t[tx][ty + 8 * i]);
    }
}

// ============================================================================
// GEMM: C tile 128x128, plain fp16, k64 chunks, 3-stage cp.async.
// ============================================================================
template <int EPI, int KR>
__global__ __launch_bounds__(256, 2)
void gemm_mma(const __half* __restrict__ A,
              const __half* __restrict__ B,
              const float* __restrict__ bias,
              float* __restrict__ OutF,
              __half* __restrict__ OutH,
              int NBtot)
{
    extern __shared__ __align__(1024) char sm[];
    __shared__ float s_bias[128];

    constexpr int NC = KR / 64;                    // k64 chunks
    constexpr size_t gStride = (size_t)64 * KR;    // bytes between seg rows (32 rows)

    const int tid = threadIdx.x;
    const int wid = tid >> 5;
    const int lid = tid & 31;
    const int warp_m = wid >> 2;
    const int warp_n = wid & 3;
    const int e = blockIdx.z;
    const int rowBase = blockIdx.y * 128;
    const int colBase = blockIdx.x * 128;
    const size_t rowGlob0 = (size_t)e * T_ + rowBase;
    const uint32_t smb = smem_u32(sm);

    if (tid < 128) s_bias[tid] = bias[(size_t)e * NBtot + colBase + tid];

    // cp.async running pointers: A/B tiles 128 rows x 128B = 1024 segs; 4+4/thread
    const int r0 = tid >> 3, g0 = tid & 7;
    const char* aCur = (const char*)(A + (rowGlob0 + r0) * (size_t)KR) + g0 * 16;
    const char* bCur = (const char*)(B + ((size_t)e * NBtot + colBase + r0) * (size_t)KR) + g0 * 16;
    const uint32_t sO0 = (uint32_t)(r0 * 128 + ((g0 << 4) ^ ((r0 & 7) << 4)));

    // ldmatrix addressing
    const int lr = (lid & 7) + ((lid >> 3) & 1) * 8;
    const uint32_t lcol = ((lid >> 4) & 1) << 4;
    const uint32_t xr = (uint32_t)(lr & 7) << 4;
    const uint32_t arb0 = (uint32_t)(warp_m * 64 + lr) * 128;
    const uint32_t brb0 = (uint32_t)(warp_n * 32 + lr) * 128 + A_BYTES;

    // k16 sub-column offsets within the 128B row
    uint32_t colq[4];
    #pragma unroll
    for (int q = 0; q < 4; q++) colq[q] = ((uint32_t)(q << 5) | lcol) ^ xr;

    float acc[4][4][4];
    #pragma unroll
    for (int m = 0; m < 4; m++)
        #pragma unroll
        for (int n = 0; n < 4; n++)
            #pragma unroll
            for (int q = 0; q < 4; q++)
                acc[m][n][q] = 0.0f;

    auto fill = [&](uint32_t sbase) {
        uint32_t sb = sbase + sO0;
        #pragma unroll
        for (int i = 0; i < 4; i++)
            cpa16(sb + i * 4096, aCur + i * gStride);
        #pragma unroll
        for (int i = 0; i < 4; i++)
            cpa16(sb + A_BYTES + i * 4096, bCur + i * gStride);
        asm volatile("cp.async.commit_group;" ::: "memory");
        aCur += 128; bCur += 128;
    };
    auto commit_empty = [&]() {
        asm volatile("cp.async.commit_group;" ::: "memory");
    };

    auto ldA = [&](uint32_t st, uint32_t col, uint32_t (&fr)[4][4]) {
        #pragma unroll
        for (int f = 0; f < 4; f++)
            ldsm_x4(fr[f], st + arb0 + f * 2048 + col);
    };
    auto ldB = [&](uint32_t st, uint32_t col, uint32_t (&fr)[2][4]) {
        #pragma unroll
        for (int g = 0; g < 2; g++)
            ldsm_x4(fr[g], st + brb0 + g * 2048 + col);
    };
    auto mmaT = [&](const uint32_t (&a)[4][4], const uint32_t (&b)[2][4]) {
        #pragma unroll
        for (int m = 0; m < 4; m++)
            #pragma unroll
            for (int n = 0; n < 4; n++)
                mma_f16(acc[m][n], a[m], b[n >> 1][n & 1], b[n >> 1][2 + (n & 1)]);
    };

    // prologue
    uint32_t st0 = smb, st1 = smb + STAGE, st2 = smb + 2 * STAGE;
    fill(st0); fill(st1); fill(st2);
    asm volatile("cp.async.wait_group 2;" ::: "memory");
    __syncthreads();

    uint32_t aF[2][4][4], bF[2][2][4];
    ldA(st0, colq[0], aF[0]);
    ldB(st0, colq[0], bF[0]);

    #pragma unroll 1
    for (int c = 0; c < NC - 1; c++) {
        const uint32_t st = st0;

        ldA(st, colq[1], aF[1]);
        ldB(st, colq[1], bF[1]);
        mmaT(aF[0], bF[0]);                // q0

        ldA(st, colq[2], aF[0]);
        ldB(st, colq[2], bF[0]);
        mmaT(aF[1], bF[1]);                // q1

        ldA(st, colq[3], aF[1]);
        ldB(st, colq[3], bF[1]);
        mmaT(aF[0], bF[0]);                // q2

        asm volatile("cp.async.wait_group 1;" ::: "memory");
        __syncthreads();
        if (c + 3 < NC) fill(st); else commit_empty();

        ldA(st1, colq[0], aF[0]);          // next chunk q0 prefetch
        mmaT(aF[1], bF[1]);                // q3 (register-only, hides barrier)
        ldB(st1, colq[0], bF[0]);

        uint32_t t = st0; st0 = st1; st1 = st2; st2 = t;
    }

    // final chunk
    {
        const uint32_t st = st0;
        ldA(st, colq[1], aF[1]);
        ldB(st, colq[1], bF[1]);
        mmaT(aF[0], bF[0]);
        ldA(st, colq[2], aF[0]);
        ldB(st, colq[2], bF[0]);
        mmaT(aF[1], bF[1]);
        ldA(st, colq[3], aF[1]);
        ldB(st, colq[3], bF[1]);
        mmaT(aF[0], bF[0]);
        mmaT(aF[1], bF[1]);
    }
    __syncthreads();

    // ---- epilogue ----
    #pragma unroll
    for (int m = 0; m < 4; m++) {
        const size_t rG = rowGlob0 + warp_m * 64 + m * 16 + (lid >> 2);
        #pragma unroll
        for (int n = 0; n < 4; n++) {
            const int cl = warp_n * 32 + n * 8 + (lid & 3) * 2;
            const float b0 = s_bias[cl], b1 = s_bias[cl + 1];
            const int cg = colBase + cl;
            #pragma unroll
            for (int h = 0; h < 2; h++) {
                float v0 = acc[m][n][2 * h + 0] + b0;
                float v1 = acc[m][n][2 * h + 1] + b1;
                const size_t rr = rG + h * 8;
                if (EPI == 1) {
                    v0 = gelu_exact(v0); v1 = gelu_exact(v1);
                    *(uint32_t*)(OutH + rr * (size_t)NBtot + cg) =
                        pk(__float2half_rn(v0), __float2half_rn(v1));
                } else {
                    *(float2*)(OutF + rr * (size_t)NBtot + cg) = make_float2(v0, v1);
                }
            }
        }
    }
}

// ============================================================================
extern "C" void kernel_launch(void* const* d_in, const int* in_sizes, int n_in,
                              void* d_out, int out_size)
{
    (void)in_sizes; (void)n_in; (void)out_size;
    const float* x  = (const float*)d_in[0];
    const float* w1 = (const float*)d_in[1];
    const float* b1 = (const float*)d_in[2];
    const float* w2 = (const float*)d_in[3];
    const float* b2 = (const float*)d_in[4];
    float* out = (float*)d_out;

    __half *x2, *w1t, *h2, *w2t;
    cudaGetSymbolAddress((void**)&x2,  g_x2);
    cudaGetSymbolAddress((void**)&w1t, g_w1t);
    cudaGetSymbolAddress((void**)&h2,  g_h2);
    cudaGetSymbolAddress((void**)&w2t, g_w2t);

    const int SMEM = NSTAGE * STAGE;   // 98304
    cudaFuncSetAttribute((const void*)gemm_mma<1, D_>,
                         cudaFuncAttributeMaxDynamicSharedMemorySize, SMEM);
    cudaFuncSetAttribute((const void*)gemm_mma<0, H_>,
                         cudaFuncAttributeMaxDynamicSharedMemorySize, SMEM);

    convert_x<<<32768, 256>>>(x, x2);
    convert_w<<<dim3(H_ / 32, D_ / 32, E_), dim3(32, 8)>>>(w1, w1t, D_, H_);
    convert_w<<<dim3(D_ / 32, H_ / 32, E_), dim3(32, 8)>>>(w2, w2t, H_, D_);

    // GEMM1: K=1024 -> h2 fp16 with bias+GELU
    gemm_mma<1, D_><<<dim3(H_ / 128, T_ / 128, E_), 256, SMEM>>>(
        x2, w1t, b1, nullptr, h2, H_);

    // GEMM2: K=2048 -> fp32 out with bias
    gemm_mma<0, H_><<<dim3(D_ / 128, T_ / 128, E_), 256, SMEM>>>(
        h2, w2t, b2, out, nullptr, D_);
}

// round 9
// speedup vs baseline: 7.2936x; 1.0133x over previous
#include <cuda_runtime.h>
#include <cuda_fp16.h>
#include <cstdint>
#include <math.h>

// ============================================================================
// Experts MLP via plain fp16 mma.sync GEMMs (fp32 accumulate).
// R9: CTA tile 128x256, warp tile 64x64 (8 warps), 1 CTA/SM.
//   LDSM:MMA ratio 1:4 (was 1:2.67) -> less LDS/ALU per tensor op.
//   x  -> x2  [32768][1024 fp16]
//   w1 -> w1t [e][n][1024 fp16]  (K-major transpose)
//   GEMM1: acc = x2 @ w1t^T + b1, exact GELU -> h2 fp16
//   w2 -> w2t [e][n][2048 fp16]
//   GEMM2: acc = h2 @ w2t^T + b2 -> fp32 out
// ============================================================================

#define E_ 8
#define T_ 4096
#define D_ 1024
#define H_ 2048

#define A_BYTES 16384              // 128 rows * 128B
#define B_BYTES 32768              // 256 rows * 128B
#define STAGE   49152              // A + B
#define NSTAGE  3

__device__ __align__(256) __half g_x2[(size_t)32768 * 1024];
__device__ __align__(256) __half g_w1t[(size_t)8 * 2048 * 1024];
__device__ __align__(256) __half g_h2[(size_t)32768 * 2048];
__device__ __align__(256) __half g_w2t[(size_t)8 * 1024 * 2048];

__device__ __forceinline__ uint32_t smem_u32(const void* p) {
    uint32_t a;
    asm("{ .reg .u64 t; cvta.to.shared.u64 t, %1; cvt.u32.u64 %0, t; }"
        : "=r"(a) : "l"(p));
    return a;
}
__device__ __forceinline__ void cpa16(uint32_t dst, const void* src) {
    asm volatile("cp.async.cg.shared.global [%0], [%1], 16;" :: "r"(dst), "l"(src));
}
__device__ __forceinline__ void ldsm_x4(uint32_t* r, uint32_t addr) {
    asm volatile("ldmatrix.sync.aligned.m8n8.x4.shared.b16 {%0,%1,%2,%3}, [%4];"
                 : "=r"(r[0]), "=r"(r[1]), "=r"(r[2]), "=r"(r[3]) : "r"(addr));
}
__device__ __forceinline__ void mma_f16(float* c, const uint32_t* a,
                                        uint32_t b0, uint32_t b1) {
    asm volatile(
        "mma.sync.aligned.m16n8k16.row.col.f32.f16.f16.f32 "
        "{%0,%1,%2,%3}, {%4,%5,%6,%7}, {%8,%9}, {%0,%1,%2,%3};"
        : "+f"(c[0]), "+f"(c[1]), "+f"(c[2]), "+f"(c[3])
        : "r"(a[0]), "r"(a[1]), "r"(a[2]), "r"(a[3]), "r"(b0), "r"(b1));
}

__device__ __forceinline__ float gelu_exact(float x) {
    return 0.5f * x * (1.0f + erff(x * 0.70710678118654752f));
}
__device__ __forceinline__ uint32_t pk(__half a, __half b) {
    return (uint32_t)__half_as_ushort(a) | ((uint32_t)__half_as_ushort(b) << 16);
}

// ============================================================================
// prepasses
// ============================================================================
__global__ void convert_x(const float* __restrict__ x, __half* __restrict__ x2) {
    size_t base = ((size_t)blockIdx.x * 256 + threadIdx.x) * 4;
    float4 v = *(const float4*)(x + base);
    uint2 o = make_uint2(pk(__float2half_rn(v.x), __float2half_rn(v.y)),
                         pk(__float2half_rn(v.z), __float2half_rn(v.w)));
    *(uint2*)(x2 + base) = o;
}

__global__ void convert_w(const float* __restrict__ w, __half* __restrict__ wt,
                          int K, int N) {
    __shared__ float t[32][33];
    const int e = blockIdx.z;
    const int nb = blockIdx.x * 32, kb = blockIdx.y * 32;
    const float* we = w + (size_t)e * K * N;
    __half* oe = wt + (size_t)e * N * K;
    const int tx = threadIdx.x, ty = threadIdx.y; // (32, 8)
    #pragma unroll
    for (int i = 0; i < 4; i++)
        t[ty + 8 * i][tx] = we[(size_t)(kb + ty + 8 * i) * N + nb + tx];
    __syncthreads();
    #pragma unroll
    for (int i = 0; i < 4; i++) {
        int n = nb + ty + 8 * i, k = kb + tx;
        oe[(size_t)n * K + k] = __float2half_rn(t[tx][ty + 8 * i]);
    }
}

// ============================================================================
// GEMM: C tile 128x256, warp 64x64, k64 chunks, 3-stage cp.async, 1 CTA/SM.
// ============================================================================
template <int EPI, int KR>
__global__ __launch_bounds__(256, 1)
void gemm_mma(const __half* __restrict__ A,
              const __half* __restrict__ B,
              const float* __restrict__ bias,
              float* __restrict__ OutF,
              __half* __restrict__ OutH,
              int NBtot)
{
    extern __shared__ __align__(1024) char sm[];
    __shared__ float s_bias[256];

    constexpr int NC = KR / 64;
    constexpr size_t gStride = (size_t)64 * KR;    // bytes between seg rows (32 rows)

    const int tid = threadIdx.x;
    const int wid = tid >> 5;
    const int lid = tid & 31;
    const int warp_m = wid >> 2;     // 0..1  (64-row half)
    const int warp_n = wid & 3;      // 0..3  (64-col quarter)
    const int e = blockIdx.z;
    const int rowBase = blockIdx.y * 128;
    const int colBase = blockIdx.x * 256;
    const size_t rowGlob0 = (size_t)e * T_ + rowBase;
    const uint32_t smb = smem_u32(sm);

    s_bias[tid] = bias[(size_t)e * NBtot + colBase + tid];

    // cp.async: A 1024 segs (4/thr), B 2048 segs (8/thr); row stride 32
    const int r0 = tid >> 3, g0 = tid & 7;
    const char* aCur = (const char*)(A + (rowGlob0 + r0) * (size_t)KR) + g0 * 16;
    const char* bCur = (const char*)(B + ((size_t)e * NBtot + colBase + r0) * (size_t)KR) + g0 * 16;
    const uint32_t sO0 = (uint32_t)(r0 * 128 + ((g0 << 4) ^ ((r0 & 7) << 4)));

    // ldmatrix addressing
    const int lr = (lid & 7) + ((lid >> 3) & 1) * 8;
    const uint32_t lcol = ((lid >> 4) & 1) << 4;
    const uint32_t xr = (uint32_t)(lr & 7) << 4;
    const uint32_t arb0 = (uint32_t)(warp_m * 64 + lr) * 128;
    const uint32_t brb0 = (uint32_t)(warp_n * 64 + lr) * 128 + A_BYTES;

    uint32_t colq[4];
    #pragma unroll
    for (int q = 0; q < 4; q++) colq[q] = ((uint32_t)(q << 5) | lcol) ^ xr;

    float acc[4][8][4];
    #pragma unroll
    for (int m = 0; m < 4; m++)
        #pragma unroll
        for (int n = 0; n < 8; n++)
            #pragma unroll
            for (int q = 0; q < 4; q++)
                acc[m][n][q] = 0.0f;

    auto fill = [&](uint32_t sbase) {
        uint32_t sb = sbase + sO0;
        #pragma unroll
        for (int i = 0; i < 4; i++)
            cpa16(sb + i * 4096, aCur + i * gStride);
        #pragma unroll
        for (int i = 0; i < 8; i++)
            cpa16(sb + A_BYTES + i * 4096, bCur + i * gStride);
        asm volatile("cp.async.commit_group;" ::: "memory");
        aCur += 128; bCur += 128;
    };
    auto commit_empty = [&]() {
        asm volatile("cp.async.commit_group;" ::: "memory");
    };

    auto ldA = [&](uint32_t st, uint32_t col, uint32_t (&fr)[4][4]) {
        #pragma unroll
        for (int f = 0; f < 4; f++)
            ldsm_x4(fr[f], st + arb0 + f * 2048 + col);
    };
    auto ldB = [&](uint32_t st, uint32_t col, uint32_t (&fr)[4][4]) {
        #pragma unroll
        for (int g = 0; g < 4; g++)
            ldsm_x4(fr[g], st + brb0 + g * 2048 + col);
    };
    auto mmaT = [&](const uint32_t (&a)[4][4], const uint32_t (&b)[4][4]) {
        #pragma unroll
        for (int m = 0; m < 4; m++)
            #pragma unroll
            for (int n = 0; n < 8; n++)
                mma_f16(acc[m][n], a[m], b[n >> 1][n & 1], b[n >> 1][2 + (n & 1)]);
    };

    // prologue
    uint32_t st0 = smb, st1 = smb + STAGE, st2 = smb + 2 * STAGE;
    fill(st0); fill(st1); fill(st2);
    asm volatile("cp.async.wait_group 2;" ::: "memory");
    __syncthreads();

    uint32_t aF[2][4][4], bF[2][4][4];
    ldA(st0, colq[0], aF[0]);
    ldB(st0, colq[0], bF[0]);

    #pragma unroll 1
    for (int c = 0; c < NC - 1; c++) {
        const uint32_t st = st0;

        ldA(st, colq[1], aF[1]);
        ldB(st, colq[1], bF[1]);
        mmaT(aF[0], bF[0]);                // q0

        ldA(st, colq[2], aF[0]);
        ldB(st, colq[2], bF[0]);
        mmaT(aF[1], bF[1]);                // q1

        ldA(st, colq[3], aF[1]);
        ldB(st, colq[3], bF[1]);
        mmaT(aF[0], bF[0]);                // q2

        asm volatile("cp.async.wait_group 1;" ::: "memory");
        __syncthreads();
        if (c + 3 < NC) fill(st); else commit_empty();

        ldA(st1, colq[0], aF[0]);          // next chunk q0 prefetch
        mmaT(aF[1], bF[1]);                // q3 (register-only, hides barrier)
        ldB(st1, colq[0], bF[0]);

        uint32_t t = st0; st0 = st1; st1 = st2; st2 = t;
    }

    // final chunk
    {
        const uint32_t st = st0;
        ldA(st, colq[1], aF[1]);
        ldB(st, colq[1], bF[1]);
        mmaT(aF[0], bF[0]);
        ldA(st, colq[2], aF[0]);
        ldB(st, colq[2], bF[0]);
        mmaT(aF[1], bF[1]);
        ldA(st, colq[3], aF[1]);
        ldB(st, colq[3], bF[1]);
        mmaT(aF[0], bF[0]);
        mmaT(aF[1], bF[1]);
    }
    __syncthreads();

    // ---- epilogue ----
    #pragma unroll
    for (int m = 0; m < 4; m++) {
        const size_t rG = rowGlob0 + warp_m * 64 + m * 16 + (lid >> 2);
        #pragma unroll
        for (int n = 0; n < 8; n++) {
            const int cl = warp_n * 64 + n * 8 + (lid & 3) * 2;
            const float b0 = s_bias[cl], b1 = s_bias[cl + 1];
            const int cg = colBase + cl;
            #pragma unroll
            for (int h = 0; h < 2; h++) {
                float v0 = acc[m][n][2 * h + 0] + b0;
                float v1 = acc[m][n][2 * h + 1] + b1;
                const size_t rr = rG + h * 8;
                if (EPI == 1) {
                    v0 = gelu_exact(v0); v1 = gelu_exact(v1);
                    *(uint32_t*)(OutH + rr * (size_t)NBtot + cg) =
                        pk(__float2half_rn(v0), __float2half_rn(v1));
                } else {
                    *(float2*)(OutF + rr * (size_t)NBtot + cg) = make_float2(v0, v1);
                }
            }
        }
    }
}

// ============================================================================
extern "C" void kernel_launch(void* const* d_in, const int* in_sizes, int n_in,
                              void* d_out, int out_size)
{
    (void)in_sizes; (void)n_in; (void)out_size;
    const float* x  = (const float*)d_in[0];
    const float* w1 = (const float*)d_in[1];
    const float* b1 = (const float*)d_in[2];
    const float* w2 = (const float*)d_in[3];
    const float* b2 = (const float*)d_in[4];
    float* out = (float*)d_out;

    __half *x2, *w1t, *h2, *w2t;
    cudaGetSymbolAddress((void**)&x2,  g_x2);
    cudaGetSymbolAddress((void**)&w1t, g_w1t);
    cudaGetSymbolAddress((void**)&h2,  g_h2);
    cudaGetSymbolAddress((void**)&w2t, g_w2t);

    const int SMEM = NSTAGE * STAGE;   // 147456
    cudaFuncSetAttribute((const void*)gemm_mma<1, D_>,
                         cudaFuncAttributeMaxDynamicSharedMemorySize, SMEM);
    cudaFuncSetAttribute((const void*)gemm_mma<0, H_>,
                         cudaFuncAttributeMaxDynamicSharedMemorySize, SMEM);

    convert_x<<<32768, 256>>>(x, x2);
    convert_w<<<dim3(H_ / 32, D_ / 32, E_), dim3(32, 8)>>>(w1, w1t, D_, H_);
    convert_w<<<dim3(D_ / 32, H_ / 32, E_), dim3(32, 8)>>>(w2, w2t, H_, D_);

    // GEMM1: K=1024, tiles 128x256 over N=2048
    gemm_mma<1, D_><<<dim3(H_ / 256, T_ / 128, E_), 256, SMEM>>>(
        x2, w1t, b1, nullptr, h2, H_);

    // GEMM2: K=2048, tiles 128x256 over N=1024
    gemm_mma<0, H_><<<dim3(D_ / 256, T_ / 128, E_), 256, SMEM>>>(
        h2, w2t, b2, out, nullptr, D_);
}